// round 9
// baseline (speedup 1.0000x reference)
#include <cuda_runtime.h>
#include <cuda_fp16.h>
#include <stdint.h>
#include <math.h>

#define kD 256
#define kH 8
#define kFF 256
#define kL 3
#define kB 32768
#define kMB 16
#define kNT 256
#define HS 264

#define XO 0
#define HAO 65536
#define WOF 99328
#define QOF 152576
#define OOF 178176
#define SMEM_BYTES 211968

__device__ __align__(16) __half g_Wqkv[kL * kD * 3 * kD];
__device__ __align__(16) __half g_Wo[kL * kD * kD];
__device__ __align__(16) __half g_W1[kL * kD * kFF];
__device__ __align__(16) __half g_W2[kL * kFF * kD];

__global__ void prep_weights_kernel(const float* __restrict__ wqkv,
                                    const float* __restrict__ wo,
                                    const float* __restrict__ w1,
                                    const float* __restrict__ w2) {
  int i = blockIdx.x * blockDim.x + threadIdx.x;
  const int NQ = kL * kD * 3 * kD, NO = kL * kD * kD;
  if (i < NQ) { g_Wqkv[i] = __float2half_rn(wqkv[i]); return; }
  i -= NQ;
  if (i < NO) { g_Wo[i] = __float2half_rn(wo[i]); return; }
  i -= NO;
  if (i < NO) { g_W1[i] = __float2half_rn(w1[i]); return; }
  i -= NO;
  if (i < NO) { g_W2[i] = __float2half_rn(w2[i]); return; }
}

__device__ __forceinline__ uint32_t smem_u32(const void* p) {
  uint32_t a;
  asm volatile("{ .reg .u64 t; cvta.to.shared.u64 t, %1; cvt.u32.u64 %0, t; }"
               : "=r"(a) : "l"(p));
  return a;
}
__device__ __forceinline__ void ldsm4(uint32_t& r0, uint32_t& r1, uint32_t& r2,
                                      uint32_t& r3, uint32_t a) {
  asm volatile("ldmatrix.sync.aligned.m8n8.x4.shared.b16 {%0,%1,%2,%3}, [%4];"
               : "=r"(r0), "=r"(r1), "=r"(r2), "=r"(r3) : "r"(a));
}
__device__ __forceinline__ void ldsm4t(uint32_t& r0, uint32_t& r1, uint32_t& r2,
                                       uint32_t& r3, uint32_t a) {
  asm volatile("ldmatrix.sync.aligned.m8n8.x4.trans.shared.b16 {%0,%1,%2,%3}, [%4];"
               : "=r"(r0), "=r"(r1), "=r"(r2), "=r"(r3) : "r"(a));
}
__device__ __forceinline__ void mma16816(float* c, uint32_t a0, uint32_t a1,
                                         uint32_t a2, uint32_t a3, uint32_t b0,
                                         uint32_t b1) {
  asm volatile(
      "mma.sync.aligned.m16n8k16.row.col.f32.f16.f16.f32 "
      "{%0,%1,%2,%3}, {%4,%5,%6,%7}, {%8,%9}, {%0,%1,%2,%3};"
      : "+f"(c[0]), "+f"(c[1]), "+f"(c[2]), "+f"(c[3])
      : "r"(a0), "r"(a1), "r"(a2), "r"(a3), "r"(b0), "r"(b1));
}

// C[64,wc-half] = A[64,256](smem fp16 stride HS) @ W[256,*](smem fp16 stride WST)
template <int NPAIR, int WST>
__device__ __forceinline__ void gemm_block(uint32_t aBase, uint32_t wBase,
                                           int warp, int lane,
                                           float acc[2 * NPAIR][4]) {
  const int wr = warp >> 1, wc = warp & 1;
#pragma unroll
  for (int i = 0; i < 2 * NPAIR; i++)
#pragma unroll
    for (int j = 0; j < 4; j++) acc[i][j] = 0.0f;
  const uint32_t aAddr =
      aBase + (uint32_t)(((16 * wr + (lane & 15)) * HS + ((lane >> 4) << 3)) << 1);
  const uint32_t bAddr =
      wBase +
      (uint32_t)(((lane & 15) * WST + wc * (NPAIR * 16) + ((lane >> 4) << 3)) << 1);
#pragma unroll
  for (int k0 = 0; k0 < kD; k0 += 16) {
    uint32_t a0, a1, a2, a3;
    ldsm4(a0, a1, a2, a3, aAddr + (uint32_t)(k0 << 1));
#pragma unroll
    for (int p = 0; p < NPAIR; p++) {
      uint32_t b0, b1, b2, b3;
      ldsm4t(b0, b1, b2, b3, bAddr + (uint32_t)((k0 * WST + p * 16) << 1));
      mma16816(acc[2 * p], a0, a1, a2, a3, b0, b1);
      mma16816(acc[2 * p + 1], a0, a1, a2, a3, b2, b3);
    }
  }
}

__device__ __forceinline__ void row_stats(const float* __restrict__ row, int lane,
                                          float v[8], float& mean, float& rstd) {
  const float4* r4 = (const float4*)row;
  float4 a = r4[lane * 2], b = r4[lane * 2 + 1];
  v[0] = a.x; v[1] = a.y; v[2] = a.z; v[3] = a.w;
  v[4] = b.x; v[5] = b.y; v[6] = b.z; v[7] = b.w;
  float s = 0.f, s2 = 0.f;
#pragma unroll
  for (int j = 0; j < 8; j++) { s += v[j]; s2 += v[j] * v[j]; }
#pragma unroll
  for (int o = 16; o > 0; o >>= 1) {
    s += __shfl_xor_sync(0xffffffffu, s, o);
    s2 += __shfl_xor_sync(0xffffffffu, s2, o);
  }
  mean = s * (1.f / 256.f);
  rstd = rsqrtf(s2 * (1.f / 256.f) - mean * mean + 1e-5f);
}

__device__ __forceinline__ void ln_to_half(const float* __restrict__ xs,
                                           __half* __restrict__ dst,
                                           const float* __restrict__ g,
                                           const float* __restrict__ bt, int tid) {
  int warp = tid >> 5, lane = tid & 31;
#pragma unroll
  for (int i = 0; i < 8; i++) {
    int r = warp * 8 + i;
    float v[8], mean, rstd;
    row_stats(xs + r * 256, lane, v, mean, rstd);
    __half2* d2 = (__half2*)(dst + r * HS + lane * 8);
#pragma unroll
    for (int j = 0; j < 4; j++) {
      int c = lane * 8 + 2 * j;
      d2[j] = __floats2half2_rn((v[2 * j] - mean) * rstd * g[c] + bt[c],
                                (v[2 * j + 1] - mean) * rstd * g[c + 1] + bt[c + 1]);
    }
  }
}

__device__ __forceinline__ void ln_inplace(float* __restrict__ xs,
                                           const float* __restrict__ g,
                                           const float* __restrict__ bt, int tid) {
  int warp = tid >> 5, lane = tid & 31;
#pragma unroll
  for (int i = 0; i < 8; i++) {
    int r = warp * 8 + i;
    float v[8], mean, rstd;
    row_stats(xs + r * 256, lane, v, mean, rstd);
#pragma unroll
    for (int j = 0; j < 8; j++) {
      int c = lane * 8 + j;
      xs[r * 256 + c] = (v[j] - mean) * rstd * g[c] + bt[c];
    }
  }
}

// gathered QKV weight tile for head h: [256][96] (q|k|v, 32 each), smem stride 104
__device__ __forceinline__ void load_wtile_qkv(__half* __restrict__ wt,
                                               const __half* __restrict__ gw,
                                               int h, int tid) {
#pragma unroll
  for (int i = 0; i < 12; i++) {
    int u = tid + kNT * i;
    int row = u / 12, j = u - row * 12;
    int part = j >> 2, sub = j & 3;
    *(uint4*)(wt + row * 104 + part * 32 + sub * 8) =
        *(const uint4*)(gw + row * 768 + part * 256 + h * 32 + sub * 8);
  }
}
// 64-col tile from [256][256] weight, smem stride 72
__device__ __forceinline__ void load_wtile_64(__half* __restrict__ wt,
                                              const __half* __restrict__ gw,
                                              int n0, int tid) {
#pragma unroll
  for (int i = 0; i < 8; i++) {
    int u = tid + kNT * i;
    int row = u >> 3, sub = u & 7;
    *(uint4*)(wt + row * 72 + sub * 8) =
        *(const uint4*)(gw + row * 256 + n0 + sub * 8);
  }
}

__global__ void __launch_bounds__(kNT, 1) fused_kernel(
    const float* __restrict__ global_emb, const float* __restrict__ pert_emb,
    const float* __restrict__ sym_feat, const float* __restrict__ ppi_feat,
    const float* __restrict__ sym_W, const float* __restrict__ sym_b,
    const float* __restrict__ sym_ln_g, const float* __restrict__ sym_ln_b,
    const float* __restrict__ tte, const float* __restrict__ bqkv,
    const float* __restrict__ bo, const float* __restrict__ ln1_g,
    const float* __restrict__ ln1_b, const float* __restrict__ ln2_g,
    const float* __restrict__ ln2_b, const float* __restrict__ b1,
    const float* __restrict__ b2, const float* __restrict__ final_g,
    const float* __restrict__ final_b, const float* __restrict__ out_g,
    const float* __restrict__ out_b, float* __restrict__ out) {
  extern __shared__ char smem[];
  float* xs = (float*)(smem + XO);
  __half* hA = (__half*)(smem + HAO);
  __half* wt = (__half*)(smem + WOF);
  float* qkvh = (float*)(smem + QOF);
  __half* oB = (__half*)(smem + OOF);

  const int tid = threadIdx.x, warp = tid >> 5, lane = tid & 31;
  const int gb0 = blockIdx.x * kMB;
  const uint32_t hA_u = smem_u32(hA), wt_u = smem_u32(wt), oB_u = smem_u32(oB);

  // ---- initial x: tokens 0,1,3 + token-type emb; stage sym_feat ----
#pragma unroll
  for (int i = 0; i < 16; i++) {
    int u = tid + kNT * i;
    int b = u >> 8, c = u & 255;
    xs[(b * 4 + 0) * 256 + c] = global_emb[(size_t)(gb0 + b) * 256 + c] + tte[c];
    xs[(b * 4 + 1) * 256 + c] = pert_emb[(size_t)(gb0 + b) * 256 + c] + tte[256 + c];
    xs[(b * 4 + 3) * 256 + c] = ppi_feat[(size_t)(gb0 + b) * 256 + c] + tte[768 + c];
  }
#pragma unroll
  for (int i = 0; i < 4; i++) {
    int u = tid + kNT * i;
    qkvh[u] = sym_feat[(size_t)gb0 * 64 + u];
  }
  __syncthreads();

  // sym projection (fp32)
#pragma unroll
  for (int i = 0; i < 16; i++) {
    int u = tid + kNT * i;
    int b = u >> 8, c = u & 255;
    const float* sf = qkvh + b * 64;
    float acc = sym_b[c];
#pragma unroll 8
    for (int k = 0; k < 64; k++) acc += sf[k] * sym_W[k * 256 + c];
    xs[(b * 4 + 2) * 256 + c] = acc;
  }
  __syncthreads();

  // sym LN + token-type emb (2 seqs per warp)
#pragma unroll
  for (int i = 0; i < 2; i++) {
    int r = (warp * 2 + i) * 4 + 2;
    float v[8], mean, rstd;
    row_stats(xs + r * 256, lane, v, mean, rstd);
#pragma unroll
    for (int j = 0; j < 8; j++) {
      int c = lane * 8 + j;
      xs[r * 256 + c] = (v[j] - mean) * rstd * sym_ln_g[c] + sym_ln_b[c] + tte[512 + c];
    }
  }
  __syncthreads();

  const int wr = warp >> 1, wc = warp & 1;
  const int r0 = 16 * wr + (lane >> 2);
  const int cl = 2 * (lane & 3);

  for (int l = 0; l < kL; l++) {
    ln_to_half(xs, hA, ln1_g + l * 256, ln1_b + l * 256, tid);
    __syncthreads();

    // ---- per-head QKV GEMM + attention ----
    for (int h = 0; h < kH; h++) {
      load_wtile_qkv(wt, g_Wqkv + (size_t)l * kD * 768, h, tid);
      __syncthreads();
      float acc[6][4];
      gemm_block<3, 104>(hA_u, wt_u, warp, lane, acc);
      const float* bq = bqkv + l * 768;
#pragma unroll
      for (int nt = 0; nt < 6; nt++) {
        int col = wc * 48 + nt * 8 + cl;
        float bv0 = bq[(col >> 5) * 256 + h * 32 + (col & 31)];
        float bv1 = bq[(col >> 5) * 256 + h * 32 + (col & 31) + 1];
        qkvh[r0 * 100 + col] = acc[nt][0] + bv0;
        qkvh[r0 * 100 + col + 1] = acc[nt][1] + bv1;
        qkvh[(r0 + 8) * 100 + col] = acc[nt][2] + bv0;
        qkvh[(r0 + 8) * 100 + col + 1] = acc[nt][3] + bv1;
      }
      __syncthreads();

      {  // attention head h: 16 threads per sequence
        const int bi = tid >> 4, rr = tid & 15;
        const int qt = rr >> 2, kt = rr & 3;
        const float* qrow = qkvh + (bi * 4 + qt) * 100;
        const float* krow = qkvh + (bi * 4 + kt) * 100 + 32;
        const float* vrow = qkvh + (bi * 4 + kt) * 100 + 64;
        float s = 0.f;
#pragma unroll
        for (int d = 0; d < 32; d++) s += qrow[d] * krow[d];
        s *= 0.17677669529663687f;
        float mx = fmaxf(s, __shfl_xor_sync(0xffffffffu, s, 1));
        mx = fmaxf(mx, __shfl_xor_sync(0xffffffffu, mx, 2));
        float p = expf(s - mx);
        float dn = p + __shfl_xor_sync(0xffffffffu, p, 1);
        dn += __shfl_xor_sync(0xffffffffu, dn, 2);
        p /= dn;
        __half* orow = oB + (bi * 4 + qt) * HS + h * 32;
#pragma unroll
        for (int d = 0; d < 32; d++) {
          float pv = p * vrow[d];
          pv += __shfl_xor_sync(0xffffffffu, pv, 1);
          pv += __shfl_xor_sync(0xffffffffu, pv, 2);
          if (kt == 0) orow[d] = __float2half_rn(pv);
        }
      }
      __syncthreads();
    }

    // ---- x += o @ Wo + bo ----
    for (int n0 = 0; n0 < 256; n0 += 64) {
      load_wtile_64(wt, g_Wo + (size_t)l * kD * kD, n0, tid);
      __syncthreads();
      float acc[4][4];
      gemm_block<2, 72>(oB_u, wt_u, warp, lane, acc);
      const float* bb = bo + l * 256;
#pragma unroll
      for (int nt = 0; nt < 4; nt++) {
        int col = n0 + wc * 32 + nt * 8 + cl;
        float bv0 = bb[col], bv1 = bb[col + 1];
        xs[r0 * 256 + col] += acc[nt][0] + bv0;
        xs[r0 * 256 + col + 1] += acc[nt][1] + bv1;
        xs[(r0 + 8) * 256 + col] += acc[nt][2] + bv0;
        xs[(r0 + 8) * 256 + col + 1] += acc[nt][3] + bv1;
      }
      __syncthreads();
    }

    ln_to_half(xs, hA, ln2_g + l * 256, ln2_b + l * 256, tid);
    __syncthreads();

    // ---- oB = gelu(h2 @ W1 + b1) ----
    for (int n0 = 0; n0 < 256; n0 += 64) {
      load_wtile_64(wt, g_W1 + (size_t)l * kD * kFF, n0, tid);
      __syncthreads();
      float acc[4][4];
      gemm_block<2, 72>(hA_u, wt_u, warp, lane, acc);
      const float* bb = b1 + l * 256;
#pragma unroll
      for (int nt = 0; nt < 4; nt++) {
        int col = n0 + wc * 32 + nt * 8 + cl;
        float bv0 = bb[col], bv1 = bb[col + 1];
#pragma unroll
        for (int q = 0; q < 2; q++) {
          int rq = r0 + q * 8;
          float v0 = acc[nt][2 * q] + bv0, v1 = acc[nt][2 * q + 1] + bv1;
          oB[rq * HS + col] =
              __float2half_rn(0.5f * v0 * (1.0f + erff(v0 * 0.7071067811865475f)));
          oB[rq * HS + col + 1] =
              __float2half_rn(0.5f * v1 * (1.0f + erff(v1 * 0.7071067811865475f)));
        }
      }
      __syncthreads();
    }

    // ---- x += oB @ W2 + b2 ----
    for (int n0 = 0; n0 < 256; n0 += 64) {
      load_wtile_64(wt, g_W2 + (size_t)l * kFF * kD, n0, tid);
      __syncthreads();
      float acc[4][4];
      gemm_block<2, 72>(oB_u, wt_u, warp, lane, acc);
      const float* bb = b2 + l * 256;
#pragma unroll
      for (int nt = 0; nt < 4; nt++) {
        int col = n0 + wc * 32 + nt * 8 + cl;
        float bv0 = bb[col], bv1 = bb[col + 1];
        xs[r0 * 256 + col] += acc[nt][0] + bv0;
        xs[r0 * 256 + col + 1] += acc[nt][1] + bv1;
        xs[(r0 + 8) * 256 + col] += acc[nt][2] + bv0;
        xs[(r0 + 8) * 256 + col + 1] += acc[nt][3] + bv1;
      }
      __syncthreads();
    }
  }

  // ---- final LN, mean over 4 tokens, output LN ----
  ln_inplace(xs, final_g, final_b, tid);
  __syncthreads();
#pragma unroll
  for (int i = 0; i < 2; i++) {
    int b = warp * 2 + i;
    const float* base = xs + b * 4 * 256;
    float v[8], s = 0.f, s2 = 0.f;
#pragma unroll
    for (int j = 0; j < 8; j++) {
      int c = lane * 8 + j;
      float m = 0.25f * (base[c] + base[256 + c] + base[512 + c] + base[768 + c]);
      v[j] = m; s += m; s2 += m * m;
    }
#pragma unroll
    for (int o = 16; o > 0; o >>= 1) {
      s += __shfl_xor_sync(0xffffffffu, s, o);
      s2 += __shfl_xor_sync(0xffffffffu, s2, o);
    }
    float mean = s * (1.f / 256.f);
    float rstd = rsqrtf(s2 * (1.f / 256.f) - mean * mean + 1e-5f);
#pragma unroll
    for (int j = 0; j < 8; j++) {
      int c = lane * 8 + j;
      out[(size_t)(gb0 + b) * 256 + c] = (v[j] - mean) * rstd * out_g[c] + out_b[c];
    }
  }
}

extern "C" void kernel_launch(void* const* d_in, const int* in_sizes, int n_in,
                              void* d_out, int out_size) {
  (void)in_sizes; (void)n_in; (void)out_size;
  const float* global_emb = (const float*)d_in[0];
  const float* pert_emb   = (const float*)d_in[1];
  const float* sym_feat   = (const float*)d_in[2];
  const float* ppi_feat   = (const float*)d_in[3];
  const float* sym_W      = (const float*)d_in[4];
  const float* sym_b      = (const float*)d_in[5];
  const float* sym_ln_g   = (const float*)d_in[6];
  const float* sym_ln_b   = (const float*)d_in[7];
  const float* tte        = (const float*)d_in[8];
  const float* Wqkv       = (const float*)d_in[9];
  const float* bqkv       = (const float*)d_in[10];
  const float* Wo         = (const float*)d_in[11];
  const float* bo         = (const float*)d_in[12];
  const float* ln1_g      = (const float*)d_in[13];
  const float* ln1_b      = (const float*)d_in[14];
  const float* ln2_g      = (const float*)d_in[15];
  const float* ln2_b      = (const float*)d_in[16];
  const float* W1         = (const float*)d_in[17];
  const float* b1         = (const float*)d_in[18];
  const float* W2         = (const float*)d_in[19];
  const float* b2         = (const float*)d_in[20];
  const float* final_g    = (const float*)d_in[21];
  const float* final_b    = (const float*)d_in[22];
  const float* out_g      = (const float*)d_in[23];
  const float* out_b      = (const float*)d_in[24];

  static bool attr_done = false;
  if (!attr_done) {
    cudaFuncSetAttribute(fused_kernel, cudaFuncAttributeMaxDynamicSharedMemorySize,
                         SMEM_BYTES);
    attr_done = true;
  }

  const int NTOT = kL * kD * 3 * kD + 3 * kL * kD * kD;  // 1179648
  prep_weights_kernel<<<(NTOT + 255) / 256, 256>>>(Wqkv, Wo, W1, W2);
  fused_kernel<<<kB / kMB, kNT, SMEM_BYTES>>>(
      global_emb, pert_emb, sym_feat, ppi_feat, sym_W, sym_b, sym_ln_g, sym_ln_b,
      tte, bqkv, bo, ln1_g, ln1_b, ln2_g, ln2_b, b1, b2, final_g, final_b, out_g,
      out_b, (float*)d_out);
}

// round 10
// speedup vs baseline: 1.1090x; 1.1090x over previous
#include <cuda_runtime.h>
#include <cuda_fp16.h>
#include <stdint.h>
#include <math.h>

#define kD 256
#define kH 8
#define kFF 256
#define kL 3
#define kB 32768
#define kMB 16
#define kNT 512
#define HS 264

#define XO 0
#define HAO 65536
#define WOF 99328
#define QOF 152576
#define OOF 178176
#define SMEM_BYTES 211968

__device__ __align__(16) __half g_Wqkv[kL * kD * 3 * kD];
__device__ __align__(16) __half g_Wo[kL * kD * kD];
__device__ __align__(16) __half g_W1[kL * kD * kFF];
__device__ __align__(16) __half g_W2[kL * kFF * kD];

__global__ void prep_weights_kernel(const float* __restrict__ wqkv,
                                    const float* __restrict__ wo,
                                    const float* __restrict__ w1,
                                    const float* __restrict__ w2) {
  int i = blockIdx.x * blockDim.x + threadIdx.x;
  const int NQ = kL * kD * 3 * kD, NO = kL * kD * kD;
  if (i < NQ) { g_Wqkv[i] = __float2half_rn(wqkv[i]); return; }
  i -= NQ;
  if (i < NO) { g_Wo[i] = __float2half_rn(wo[i]); return; }
  i -= NO;
  if (i < NO) { g_W1[i] = __float2half_rn(w1[i]); return; }
  i -= NO;
  if (i < NO) { g_W2[i] = __float2half_rn(w2[i]); return; }
}

__device__ __forceinline__ uint32_t smem_u32(const void* p) {
  uint32_t a;
  asm volatile("{ .reg .u64 t; cvta.to.shared.u64 t, %1; cvt.u32.u64 %0, t; }"
               : "=r"(a) : "l"(p));
  return a;
}
__device__ __forceinline__ void ldsm4(uint32_t& r0, uint32_t& r1, uint32_t& r2,
                                      uint32_t& r3, uint32_t a) {
  asm volatile("ldmatrix.sync.aligned.m8n8.x4.shared.b16 {%0,%1,%2,%3}, [%4];"
               : "=r"(r0), "=r"(r1), "=r"(r2), "=r"(r3) : "r"(a));
}
__device__ __forceinline__ void ldsm4t(uint32_t& r0, uint32_t& r1, uint32_t& r2,
                                       uint32_t& r3, uint32_t a) {
  asm volatile("ldmatrix.sync.aligned.m8n8.x4.trans.shared.b16 {%0,%1,%2,%3}, [%4];"
               : "=r"(r0), "=r"(r1), "=r"(r2), "=r"(r3) : "r"(a));
}
__device__ __forceinline__ void ldsm2t(uint32_t& r0, uint32_t& r1, uint32_t a) {
  asm volatile("ldmatrix.sync.aligned.m8n8.x2.trans.shared.b16 {%0,%1}, [%2];"
               : "=r"(r0), "=r"(r1) : "r"(a));
}
__device__ __forceinline__ void mma16816(float* c, uint32_t a0, uint32_t a1,
                                         uint32_t a2, uint32_t a3, uint32_t b0,
                                         uint32_t b1) {
  asm volatile(
      "mma.sync.aligned.m16n8k16.row.col.f32.f16.f16.f32 "
      "{%0,%1,%2,%3}, {%4,%5,%6,%7}, {%8,%9}, {%0,%1,%2,%3};"
      : "+f"(c[0]), "+f"(c[1]), "+f"(c[2]), "+f"(c[3])
      : "r"(a0), "r"(a1), "r"(a2), "r"(a3), "r"(b0), "r"(b1));
}

// C warp tile: rows [16*wr,16*wr+16), cols [wc*N8*8, wc*N8*8 + N8*8)
// A[64,256] fp16 smem stride HS; W[256,*] fp16 smem stride WST.
template <int N8, int WST>
__device__ __forceinline__ void gemm_block(uint32_t aBase, uint32_t wBase,
                                           int warp, int lane, float acc[N8][4]) {
  const int wr = warp >> 2, wc = warp & 3;
#pragma unroll
  for (int i = 0; i < N8; i++)
#pragma unroll
    for (int j = 0; j < 4; j++) acc[i][j] = 0.0f;
  const int bCol = wc * (N8 * 8);
  const uint32_t aAddr =
      aBase + (uint32_t)(((16 * wr + (lane & 15)) * HS + ((lane >> 4) << 3)) << 1);
  const uint32_t bAddr =
      wBase + (uint32_t)(((lane & 15) * WST + bCol + ((lane >> 4) << 3)) << 1);
#pragma unroll
  for (int k0 = 0; k0 < kD; k0 += 16) {
    uint32_t a0, a1, a2, a3;
    ldsm4(a0, a1, a2, a3, aAddr + (uint32_t)(k0 << 1));
#pragma unroll
    for (int p = 0; p < N8 / 2; p++) {
      uint32_t b0, b1, b2, b3;
      ldsm4t(b0, b1, b2, b3, bAddr + (uint32_t)((k0 * WST + p * 16) << 1));
      mma16816(acc[2 * p], a0, a1, a2, a3, b0, b1);
      mma16816(acc[2 * p + 1], a0, a1, a2, a3, b2, b3);
    }
    if (N8 & 1) {
      uint32_t b0, b1;
      uint32_t t = wBase + (uint32_t)(((lane & 15) * WST + bCol + (N8 - 1) * 8 +
                                       k0 * WST) << 1);
      ldsm2t(b0, b1, t);
      mma16816(acc[N8 - 1], a0, a1, a2, a3, b0, b1);
    }
  }
}

__device__ __forceinline__ void row_stats(const float* __restrict__ row, int lane,
                                          float v[8], float& mean, float& rstd) {
  const float4* r4 = (const float4*)row;
  float4 a = r4[lane * 2], b = r4[lane * 2 + 1];
  v[0] = a.x; v[1] = a.y; v[2] = a.z; v[3] = a.w;
  v[4] = b.x; v[5] = b.y; v[6] = b.z; v[7] = b.w;
  float s = 0.f, s2 = 0.f;
#pragma unroll
  for (int j = 0; j < 8; j++) { s += v[j]; s2 += v[j] * v[j]; }
#pragma unroll
  for (int o = 16; o > 0; o >>= 1) {
    s += __shfl_xor_sync(0xffffffffu, s, o);
    s2 += __shfl_xor_sync(0xffffffffu, s2, o);
  }
  mean = s * (1.f / 256.f);
  rstd = rsqrtf(s2 * (1.f / 256.f) - mean * mean + 1e-5f);
}

__device__ __forceinline__ void ln_to_half(const float* __restrict__ xs,
                                           __half* __restrict__ dst,
                                           const float* __restrict__ g,
                                           const float* __restrict__ bt, int tid) {
  int warp = tid >> 5, lane = tid & 31;
#pragma unroll
  for (int i = 0; i < 4; i++) {
    int r = warp * 4 + i;
    float v[8], mean, rstd;
    row_stats(xs + r * 256, lane, v, mean, rstd);
    __half2* d2 = (__half2*)(dst + r * HS + lane * 8);
#pragma unroll
    for (int j = 0; j < 4; j++) {
      int c = lane * 8 + 2 * j;
      d2[j] = __floats2half2_rn((v[2 * j] - mean) * rstd * g[c] + bt[c],
                                (v[2 * j + 1] - mean) * rstd * g[c + 1] + bt[c + 1]);
    }
  }
}

__device__ __forceinline__ void ln_inplace(float* __restrict__ xs,
                                           const float* __restrict__ g,
                                           const float* __restrict__ bt, int tid) {
  int warp = tid >> 5, lane = tid & 31;
#pragma unroll
  for (int i = 0; i < 4; i++) {
    int r = warp * 4 + i;
    float v[8], mean, rstd;
    row_stats(xs + r * 256, lane, v, mean, rstd);
#pragma unroll
    for (int j = 0; j < 8; j++) {
      int c = lane * 8 + j;
      xs[r * 256 + c] = (v[j] - mean) * rstd * g[c] + bt[c];
    }
  }
}

// gathered QKV weight tile for head h: [256][96] (q|k|v, 32 each), smem stride 104
__device__ __forceinline__ void load_wtile_qkv(__half* __restrict__ wt,
                                               const __half* __restrict__ gw,
                                               int h, int tid) {
#pragma unroll
  for (int i = 0; i < 6; i++) {
    int u = tid + kNT * i;
    int row = u / 12, j = u - row * 12;
    int part = j >> 2, sub = j & 3;
    *(uint4*)(wt + row * 104 + part * 32 + sub * 8) =
        *(const uint4*)(gw + row * 768 + part * 256 + h * 32 + sub * 8);
  }
}
// 64-col tile from [256][256] weight, smem stride 72
__device__ __forceinline__ void load_wtile_64(__half* __restrict__ wt,
                                              const __half* __restrict__ gw,
                                              int n0, int tid) {
#pragma unroll
  for (int i = 0; i < 4; i++) {
    int u = tid + kNT * i;
    int row = u >> 3, sub = u & 7;
    *(uint4*)(wt + row * 72 + sub * 8) =
        *(const uint4*)(gw + row * 256 + n0 + sub * 8);
  }
}

__global__ void __launch_bounds__(kNT, 1) fused_kernel(
    const float* __restrict__ global_emb, const float* __restrict__ pert_emb,
    const float* __restrict__ sym_feat, const float* __restrict__ ppi_feat,
    const float* __restrict__ sym_W, const float* __restrict__ sym_b,
    const float* __restrict__ sym_ln_g, const float* __restrict__ sym_ln_b,
    const float* __restrict__ tte, const float* __restrict__ bqkv,
    const float* __restrict__ bo, const float* __restrict__ ln1_g,
    const float* __restrict__ ln1_b, const float* __restrict__ ln2_g,
    const float* __restrict__ ln2_b, const float* __restrict__ b1,
    const float* __restrict__ b2, const float* __restrict__ final_g,
    const float* __restrict__ final_b, const float* __restrict__ out_g,
    const float* __restrict__ out_b, float* __restrict__ out) {
  extern __shared__ char smem[];
  float* xs = (float*)(smem + XO);
  __half* hA = (__half*)(smem + HAO);
  __half* wt = (__half*)(smem + WOF);
  float* qkvh = (float*)(smem + QOF);
  __half* oB = (__half*)(smem + OOF);

  const int tid = threadIdx.x, warp = tid >> 5, lane = tid & 31;
  const int gb0 = blockIdx.x * kMB;
  const uint32_t hA_u = smem_u32(hA), wt_u = smem_u32(wt), oB_u = smem_u32(oB);

  // ---- initial x: tokens 0,1,3 + token-type emb; stage sym_feat ----
#pragma unroll
  for (int i = 0; i < 8; i++) {
    int u = tid + kNT * i;
    int b = u >> 8, c = u & 255;
    xs[(b * 4 + 0) * 256 + c] = global_emb[(size_t)(gb0 + b) * 256 + c] + tte[c];
    xs[(b * 4 + 1) * 256 + c] = pert_emb[(size_t)(gb0 + b) * 256 + c] + tte[256 + c];
    xs[(b * 4 + 3) * 256 + c] = ppi_feat[(size_t)(gb0 + b) * 256 + c] + tte[768 + c];
  }
#pragma unroll
  for (int i = 0; i < 2; i++) {
    int u = tid + kNT * i;
    qkvh[u] = sym_feat[(size_t)gb0 * 64 + u];
  }
  __syncthreads();

  // sym projection (fp32)
#pragma unroll
  for (int i = 0; i < 8; i++) {
    int u = tid + kNT * i;
    int b = u >> 8, c = u & 255;
    const float* sf = qkvh + b * 64;
    float acc = sym_b[c];
#pragma unroll 8
    for (int k = 0; k < 64; k++) acc += sf[k] * sym_W[k * 256 + c];
    xs[(b * 4 + 2) * 256 + c] = acc;
  }
  __syncthreads();

  // sym LN + token-type emb (1 seq per warp)
  {
    int r = warp * 4 + 2;
    float v[8], mean, rstd;
    row_stats(xs + r * 256, lane, v, mean, rstd);
#pragma unroll
    for (int j = 0; j < 8; j++) {
      int c = lane * 8 + j;
      xs[r * 256 + c] = (v[j] - mean) * rstd * sym_ln_g[c] + sym_ln_b[c] + tte[512 + c];
    }
  }
  __syncthreads();

  const int wr = warp >> 2, wc = warp & 3;
  const int r0 = 16 * wr + (lane >> 2);
  const int cl = 2 * (lane & 3);

  for (int l = 0; l < kL; l++) {
    ln_to_half(xs, hA, ln1_g + l * 256, ln1_b + l * 256, tid);
    __syncthreads();

    // ---- per-head QKV GEMM + attention ----
    for (int h = 0; h < kH; h++) {
      load_wtile_qkv(wt, g_Wqkv + (size_t)l * kD * 768, h, tid);
      __syncthreads();
      float acc[3][4];
      gemm_block<3, 104>(hA_u, wt_u, warp, lane, acc);
      const float* bq = bqkv + l * 768;
#pragma unroll
      for (int t = 0; t < 3; t++) {
        int col = wc * 24 + t * 8 + cl;
        float bv0 = bq[(col >> 5) * 256 + h * 32 + (col & 31)];
        float bv1 = bq[(col >> 5) * 256 + h * 32 + (col & 31) + 1];
        qkvh[r0 * 100 + col] = acc[t][0] + bv0;
        qkvh[r0 * 100 + col + 1] = acc[t][1] + bv1;
        qkvh[(r0 + 8) * 100 + col] = acc[t][2] + bv0;
        qkvh[(r0 + 8) * 100 + col + 1] = acc[t][3] + bv1;
      }
      __syncthreads();

      {  // attention head h: one warp per sequence (bi = warp)
        const int bi = warp;
        const int qt = lane >> 3, kt = (lane >> 1) & 3, dh = lane & 1;
        const float* qrow = qkvh + (bi * 4 + qt) * 100 + dh * 16;
        const float* krow = qkvh + (bi * 4 + kt) * 100 + 32 + dh * 16;
        const float* vrow = qkvh + (bi * 4 + kt) * 100 + 64 + dh * 16;
        float s = 0.f;
#pragma unroll
        for (int d = 0; d < 16; d++) s += qrow[d] * krow[d];
        s += __shfl_xor_sync(0xffffffffu, s, 1);
        s *= 0.17677669529663687f;
        float mx = fmaxf(s, __shfl_xor_sync(0xffffffffu, s, 2));
        mx = fmaxf(mx, __shfl_xor_sync(0xffffffffu, mx, 4));
        float p = expf(s - mx);
        float dn = p + __shfl_xor_sync(0xffffffffu, p, 2);
        dn += __shfl_xor_sync(0xffffffffu, dn, 4);
        p /= dn;
        float pvout[16];
#pragma unroll
        for (int d = 0; d < 16; d++) {
          float pv = p * vrow[d];
          pv += __shfl_xor_sync(0xffffffffu, pv, 2);
          pv += __shfl_xor_sync(0xffffffffu, pv, 4);
          pvout[d] = pv;
        }
        if (kt == 0) {
          __half2* o2 = (__half2*)(oB + (bi * 4 + qt) * HS + h * 32 + dh * 16);
#pragma unroll
          for (int d = 0; d < 8; d++)
            o2[d] = __floats2half2_rn(pvout[2 * d], pvout[2 * d + 1]);
        }
      }
      __syncthreads();
    }

    // ---- x += o @ Wo + bo ----
    for (int n0 = 0; n0 < 256; n0 += 64) {
      load_wtile_64(wt, g_Wo + (size_t)l * kD * kD, n0, tid);
      __syncthreads();
      float acc[2][4];
      gemm_block<2, 72>(oB_u, wt_u, warp, lane, acc);
      const float* bb = bo + l * 256;
#pragma unroll
      for (int t = 0; t < 2; t++) {
        int col = n0 + wc * 16 + t * 8 + cl;
        float bv0 = bb[col], bv1 = bb[col + 1];
        xs[r0 * 256 + col] += acc[t][0] + bv0;
        xs[r0 * 256 + col + 1] += acc[t][1] + bv1;
        xs[(r0 + 8) * 256 + col] += acc[t][2] + bv0;
        xs[(r0 + 8) * 256 + col + 1] += acc[t][3] + bv1;
      }
      __syncthreads();
    }

    ln_to_half(xs, hA, ln2_g + l * 256, ln2_b + l * 256, tid);
    __syncthreads();

    // ---- oB = gelu(h2 @ W1 + b1) ----
    for (int n0 = 0; n0 < 256; n0 += 64) {
      load_wtile_64(wt, g_W1 + (size_t)l * kD * kFF, n0, tid);
      __syncthreads();
      float acc[2][4];
      gemm_block<2, 72>(hA_u, wt_u, warp, lane, acc);
      const float* bb = b1 + l * 256;
#pragma unroll
      for (int t = 0; t < 2; t++) {
        int col = n0 + wc * 16 + t * 8 + cl;
        float bv0 = bb[col], bv1 = bb[col + 1];
#pragma unroll
        for (int q = 0; q < 2; q++) {
          int rq = r0 + q * 8;
          float v0 = acc[t][2 * q] + bv0, v1 = acc[t][2 * q + 1] + bv1;
          oB[rq * HS + col] =
              __float2half_rn(0.5f * v0 * (1.0f + erff(v0 * 0.7071067811865475f)));
          oB[rq * HS + col + 1] =
              __float2half_rn(0.5f * v1 * (1.0f + erff(v1 * 0.7071067811865475f)));
        }
      }
      __syncthreads();
    }

    // ---- x += oB @ W2 + b2 ----
    for (int n0 = 0; n0 < 256; n0 += 64) {
      load_wtile_64(wt, g_W2 + (size_t)l * kFF * kD, n0, tid);
      __syncthreads();
      float acc[2][4];
      gemm_block<2, 72>(oB_u, wt_u, warp, lane, acc);
      const float* bb = b2 + l * 256;
#pragma unroll
      for (int t = 0; t < 2; t++) {
        int col = n0 + wc * 16 + t * 8 + cl;
        float bv0 = bb[col], bv1 = bb[col + 1];
        xs[r0 * 256 + col] += acc[t][0] + bv0;
        xs[r0 * 256 + col + 1] += acc[t][1] + bv1;
        xs[(r0 + 8) * 256 + col] += acc[t][2] + bv0;
        xs[(r0 + 8) * 256 + col + 1] += acc[t][3] + bv1;
      }
      __syncthreads();
    }
  }

  // ---- final LN, mean over 4 tokens, output LN ----
  ln_inplace(xs, final_g, final_b, tid);
  __syncthreads();
  {
    int b = warp;
    const float* base = xs + b * 4 * 256;
    float v[8], s = 0.f, s2 = 0.f;
#pragma unroll
    for (int j = 0; j < 8; j++) {
      int c = lane * 8 + j;
      float m = 0.25f * (base[c] + base[256 + c] + base[512 + c] + base[768 + c]);
      v[j] = m; s += m; s2 += m * m;
    }
#pragma unroll
    for (int o = 16; o > 0; o >>= 1) {
      s += __shfl_xor_sync(0xffffffffu, s, o);
      s2 += __shfl_xor_sync(0xffffffffu, s2, o);
    }
    float mean = s * (1.f / 256.f);
    float rstd = rsqrtf(s2 * (1.f / 256.f) - mean * mean + 1e-5f);
#pragma unroll
    for (int j = 0; j < 8; j++) {
      int c = lane * 8 + j;
      out[(size_t)(gb0 + b) * 256 + c] = (v[j] - mean) * rstd * out_g[c] + out_b[c];
    }
  }
}

extern "C" void kernel_launch(void* const* d_in, const int* in_sizes, int n_in,
                              void* d_out, int out_size) {
  (void)in_sizes; (void)n_in; (void)out_size;
  const float* global_emb = (const float*)d_in[0];
  const float* pert_emb   = (const float*)d_in[1];
  const float* sym_feat   = (const float*)d_in[2];
  const float* ppi_feat   = (const float*)d_in[3];
  const float* sym_W      = (const float*)d_in[4];
  const float* sym_b      = (const float*)d_in[5];
  const float* sym_ln_g   = (const float*)d_in[6];
  const float* sym_ln_b   = (const float*)d_in[7];
  const float* tte        = (const float*)d_in[8];
  const float* Wqkv       = (const float*)d_in[9];
  const float* bqkv       = (const float*)d_in[10];
  const float* Wo         = (const float*)d_in[11];
  const float* bo         = (const float*)d_in[12];
  const float* ln1_g      = (const float*)d_in[13];
  const float* ln1_b      = (const float*)d_in[14];
  const float* ln2_g      = (const float*)d_in[15];
  const float* ln2_b      = (const float*)d_in[16];
  const float* W1         = (const float*)d_in[17];
  const float* b1         = (const float*)d_in[18];
  const float* W2         = (const float*)d_in[19];
  const float* b2         = (const float*)d_in[20];
  const float* final_g    = (const float*)d_in[21];
  const float* final_b    = (const float*)d_in[22];
  const float* out_g      = (const float*)d_in[23];
  const float* out_b      = (const float*)d_in[24];

  static bool attr_done = false;
  if (!attr_done) {
    cudaFuncSetAttribute(fused_kernel, cudaFuncAttributeMaxDynamicSharedMemorySize,
                         SMEM_BYTES);
    attr_done = true;
  }

  const int NTOT = kL * kD * 3 * kD + 3 * kL * kD * kD;
  prep_weights_kernel<<<(NTOT + 255) / 256, 256>>>(Wqkv, Wo, W1, W2);
  fused_kernel<<<kB / kMB, kNT, SMEM_BYTES>>>(
      global_emb, pert_emb, sym_feat, ppi_feat, sym_W, sym_b, sym_ln_g, sym_ln_b,
      tte, bqkv, bo, ln1_g, ln1_b, ln2_g, ln2_b, b1, b2, final_g, final_b, out_g,
      out_b, (float*)d_out);
}

// round 11
// speedup vs baseline: 1.4041x; 1.2661x over previous
#include <cuda_runtime.h>
#include <cuda_fp16.h>
#include <stdint.h>
#include <math.h>

#define kD 256
#define kH 8
#define kL 3
#define kB 32768
#define kMB 16
#define kNT 512
#define HS 264    // A-operand half stride
#define XSD 260   // xs float stride (conflict-free epilogue)
#define QS 200    // qkvh16 half stride (2 heads: q|k|v q|k|v)
#define WQS 216   // qkv weight-chunk half stride
#define WWS 264   // square weight-chunk half stride

#define XO 0
#define HAO 66560
#define WOF 100352
#define WBUF 33792
#define QOF 167936
#define OOF 193536
#define SMEM_BYTES 227328

__device__ __align__(16) __half g_Wqkv[kL * kD * 3 * kD];
__device__ __align__(16) __half g_Wo[kL * kD * kD];
__device__ __align__(16) __half g_W1[kL * kD * kD];
__device__ __align__(16) __half g_W2[kL * kD * kD];

__global__ void prep_weights_kernel(const float* __restrict__ wqkv,
                                    const float* __restrict__ wo,
                                    const float* __restrict__ w1,
                                    const float* __restrict__ w2) {
  int i = blockIdx.x * blockDim.x + threadIdx.x;
  const int NQ = kL * kD * 3 * kD, NO = kL * kD * kD;
  if (i < NQ) { g_Wqkv[i] = __float2half_rn(wqkv[i]); return; }
  i -= NQ;
  if (i < NO) { g_Wo[i] = __float2half_rn(wo[i]); return; }
  i -= NO;
  if (i < NO) { g_W1[i] = __float2half_rn(w1[i]); return; }
  i -= NO;
  if (i < NO) { g_W2[i] = __float2half_rn(w2[i]); return; }
}

__device__ __forceinline__ uint32_t smem_u32(const void* p) {
  uint32_t a;
  asm volatile("{ .reg .u64 t; cvta.to.shared.u64 t, %1; cvt.u32.u64 %0, t; }"
               : "=r"(a) : "l"(p));
  return a;
}
__device__ __forceinline__ void ldsm4(uint32_t& r0, uint32_t& r1, uint32_t& r2,
                                      uint32_t& r3, uint32_t a) {
  asm volatile("ldmatrix.sync.aligned.m8n8.x4.shared.b16 {%0,%1,%2,%3}, [%4];"
               : "=r"(r0), "=r"(r1), "=r"(r2), "=r"(r3) : "r"(a));
}
__device__ __forceinline__ void ldsm4t(uint32_t& r0, uint32_t& r1, uint32_t& r2,
                                       uint32_t& r3, uint32_t a) {
  asm volatile("ldmatrix.sync.aligned.m8n8.x4.trans.shared.b16 {%0,%1,%2,%3}, [%4];"
               : "=r"(r0), "=r"(r1), "=r"(r2), "=r"(r3) : "r"(a));
}
__device__ __forceinline__ void mma16816(float* c, uint32_t a0, uint32_t a1,
                                         uint32_t a2, uint32_t a3, uint32_t b0,
                                         uint32_t b1) {
  asm volatile(
      "mma.sync.aligned.m16n8k16.row.col.f32.f16.f16.f32 "
      "{%0,%1,%2,%3}, {%4,%5,%6,%7}, {%8,%9}, {%0,%1,%2,%3};"
      : "+f"(c[0]), "+f"(c[1]), "+f"(c[2]), "+f"(c[3])
      : "r"(a0), "r"(a1), "r"(a2), "r"(a3), "r"(b0), "r"(b1));
}
__device__ __forceinline__ void cp16(uint32_t dst, const void* src) {
  asm volatile("cp.async.cg.shared.global [%0], [%1], 16;" :: "r"(dst), "l"(src));
}
__device__ __forceinline__ void cp_commit() {
  asm volatile("cp.async.commit_group;");
}
template <int N>
__device__ __forceinline__ void cp_wait() {
  asm volatile("cp.async.wait_group %0;" :: "n"(N));
}

__device__ __forceinline__ void row_stats(const float* __restrict__ row, int lane,
                                          float v[8], float& mean, float& rstd) {
  const float4* r4 = (const float4*)row;
  float4 a = r4[lane * 2], b = r4[lane * 2 + 1];
  v[0] = a.x; v[1] = a.y; v[2] = a.z; v[3] = a.w;
  v[4] = b.x; v[5] = b.y; v[6] = b.z; v[7] = b.w;
  float s = 0.f, s2 = 0.f;
#pragma unroll
  for (int j = 0; j < 8; j++) { s += v[j]; s2 += v[j] * v[j]; }
#pragma unroll
  for (int o = 16; o > 0; o >>= 1) {
    s += __shfl_xor_sync(0xffffffffu, s, o);
    s2 += __shfl_xor_sync(0xffffffffu, s2, o);
  }
  mean = s * (1.f / 256.f);
  rstd = rsqrtf(s2 * (1.f / 256.f) - mean * mean + 1e-5f);
}

__device__ __forceinline__ void ln_to_half(const float* __restrict__ xs,
                                           __half* __restrict__ dst,
                                           const float* __restrict__ g,
                                           const float* __restrict__ bt, int tid) {
  int warp = tid >> 5, lane = tid & 31;
#pragma unroll
  for (int i = 0; i < 4; i++) {
    int r = warp * 4 + i;
    float v[8], mean, rstd;
    row_stats(xs + r * XSD, lane, v, mean, rstd);
    __half2* d2 = (__half2*)(dst + r * HS + lane * 8);
#pragma unroll
    for (int j = 0; j < 4; j++) {
      int c = lane * 8 + 2 * j;
      d2[j] = __floats2half2_rn((v[2 * j] - mean) * rstd * g[c] + bt[c],
                                (v[2 * j + 1] - mean) * rstd * g[c + 1] + bt[c + 1]);
    }
  }
}

__device__ __forceinline__ void ln_inplace(float* __restrict__ xs,
                                           const float* __restrict__ g,
                                           const float* __restrict__ bt, int tid) {
  int warp = tid >> 5, lane = tid & 31;
#pragma unroll
  for (int i = 0; i < 4; i++) {
    int r = warp * 4 + i;
    float v[8], mean, rstd;
    row_stats(xs + r * XSD, lane, v, mean, rstd);
#pragma unroll
    for (int j = 0; j < 8; j++) {
      int c = lane * 8 + j;
      xs[r * XSD + c] = (v[j] - mean) * rstd * g[c] + bt[c];
    }
  }
}

// chunk c (64 k-rows) of square W[256][256] -> buf, half stride WWS. 2048 cp16.
__device__ __forceinline__ void load_chunk_w(uint32_t buf, const __half* __restrict__ gw,
                                             int c, int tid) {
#pragma unroll
  for (int i = 0; i < 4; i++) {
    int u = tid + kNT * i;
    int r = u >> 5, s = u & 31;
    cp16(buf + (uint32_t)((r * WWS + s * 8) << 1),
         gw + (size_t)(c * 64 + r) * 256 + s * 8);
  }
}
// chunk c of gathered QKV pair p: cols [head 2p: q|k|v][head 2p+1: q|k|v] = 192.
__device__ __forceinline__ void load_chunk_qkv(uint32_t buf, const __half* __restrict__ gw,
                                               int p, int c, int tid) {
#pragma unroll
  for (int i = 0; i < 3; i++) {
    int u = tid + kNT * i;       // 0..1535
    int r = u / 24, j = u - r * 24;
    int hp = j / 12, jm = j % 12, part = jm >> 2, sub = jm & 3;
    cp16(buf + (uint32_t)((r * WQS + j * 8) << 1),
         gw + (size_t)(c * 64 + r) * 768 + part * 256 + (2 * p + hp) * 32 + sub * 8);
  }
}

__global__ void __launch_bounds__(kNT, 1) fused_kernel(
    const float* __restrict__ global_emb, const float* __restrict__ pert_emb,
    const float* __restrict__ sym_feat, const float* __restrict__ ppi_feat,
    const float* __restrict__ sym_W, const float* __restrict__ sym_b,
    const float* __restrict__ sym_ln_g, const float* __restrict__ sym_ln_b,
    const float* __restrict__ tte, const float* __restrict__ bqkv,
    const float* __restrict__ bo, const float* __restrict__ ln1_g,
    const float* __restrict__ ln1_b, const float* __restrict__ ln2_g,
    const float* __restrict__ ln2_b, const float* __restrict__ b1,
    const float* __restrict__ b2, const float* __restrict__ final_g,
    const float* __restrict__ final_b, const float* __restrict__ out_g,
    const float* __restrict__ out_b, float* __restrict__ out) {
  extern __shared__ char smem[];
  float* xs = (float*)(smem + XO);
  __half* hA = (__half*)(smem + HAO);
  __half* qk16 = (__half*)(smem + QOF);
  __half* oB = (__half*)(smem + OOF);

  const int tid = threadIdx.x, warp = tid >> 5, lane = tid & 31;
  const int gb0 = blockIdx.x * kMB;
  const uint32_t hA_u = smem_u32(hA), oB_u = smem_u32(oB);
  const uint32_t wtU[2] = {smem_u32(smem + WOF), smem_u32(smem + WOF) + WBUF};

  // ---- initial x (stride XSD): tokens 0,1,3 + tte; stage sym_feat ----
#pragma unroll
  for (int i = 0; i < 8; i++) {
    int u = tid + kNT * i;
    int b = u >> 8, c = u & 255;
    xs[(b * 4 + 0) * XSD + c] = global_emb[(size_t)(gb0 + b) * 256 + c] + tte[c];
    xs[(b * 4 + 1) * XSD + c] = pert_emb[(size_t)(gb0 + b) * 256 + c] + tte[256 + c];
    xs[(b * 4 + 3) * XSD + c] = ppi_feat[(size_t)(gb0 + b) * 256 + c] + tte[768 + c];
  }
  {
    float* stage = (float*)qk16;  // scratch before fp16 use
#pragma unroll
    for (int i = 0; i < 2; i++) {
      int u = tid + kNT * i;
      stage[u] = sym_feat[(size_t)gb0 * 64 + u];
    }
  }
  __syncthreads();
  {  // sym projection fp32
    const float* stage = (const float*)qk16;
#pragma unroll
    for (int i = 0; i < 8; i++) {
      int u = tid + kNT * i;
      int b = u >> 8, c = u & 255;
      const float* sf = stage + b * 64;
      float acc = sym_b[c];
#pragma unroll 8
      for (int k = 0; k < 64; k++) acc += sf[k] * sym_W[k * 256 + c];
      xs[(b * 4 + 2) * XSD + c] = acc;
    }
  }
  __syncthreads();
  {  // sym LN + tte (1 seq per warp)
    int r = warp * 4 + 2;
    float v[8], mean, rstd;
    row_stats(xs + r * XSD, lane, v, mean, rstd);
#pragma unroll
    for (int j = 0; j < 8; j++) {
      int c = lane * 8 + j;
      xs[r * XSD + c] = (v[j] - mean) * rstd * sym_ln_g[c] + sym_ln_b[c] + tte[512 + c];
    }
  }
  __syncthreads();

  for (int l = 0; l < kL; l++) {
    ln_to_half(xs, hA, ln1_g + l * 256, ln1_b + l * 256, tid);
    __syncthreads();

    // ================= QKV: 4 head-pairs =================
    const __half* wq = g_Wqkv + (size_t)l * kD * 768;
    for (int p = 0; p < 4; p++) {
      load_chunk_qkv(wtU[0], wq, p, 0, tid);
      cp_commit();
      // warp grid 4 bands x 4 colgroups of 48
      const int wr = warp >> 2, wc = warp & 3;
      float acc[6][4];
#pragma unroll
      for (int i = 0; i < 6; i++)
#pragma unroll
        for (int j = 0; j < 4; j++) acc[i][j] = 0.f;
      const uint32_t aA =
          hA_u + (uint32_t)(((16 * wr + (lane & 15)) * HS + ((lane >> 4) << 3)) << 1);
      const uint32_t bOff =
          (uint32_t)(((lane & 15) * WQS + wc * 48 + ((lane >> 4) << 3)) << 1);
      for (int c = 0; c < 4; c++) {
        if (c < 3) {
          load_chunk_qkv(wtU[(c + 1) & 1], wq, p, c + 1, tid);
          cp_commit();
          cp_wait<1>();
        } else {
          cp_wait<0>();
        }
        __syncthreads();
        const uint32_t bA = wtU[c & 1] + bOff;
#pragma unroll
        for (int kl = 0; kl < 64; kl += 16) {
          uint32_t a0, a1, a2, a3;
          ldsm4(a0, a1, a2, a3, aA + (uint32_t)((c * 64 + kl) << 1));
#pragma unroll
          for (int n2 = 0; n2 < 3; n2++) {
            uint32_t b0, b1, b2, b3;
            ldsm4t(b0, b1, b2, b3, bA + (uint32_t)((kl * WQS + n2 * 16) << 1));
            mma16816(acc[2 * n2], a0, a1, a2, a3, b0, b1);
            mma16816(acc[2 * n2 + 1], a0, a1, a2, a3, b2, b3);
          }
        }
        __syncthreads();
      }
      // epilogue -> qk16 fp16 (+bias)
      const float* bq = bqkv + l * 768;
      const int r0 = 16 * wr + (lane >> 2);
      const int cl = 2 * (lane & 3);
#pragma unroll
      for (int t = 0; t < 6; t++) {
        int col = wc * 48 + t * 8 + cl;               // 0..191, even
        int head = 2 * p + (col >= 96), cm = col % 96;
        float bv0 = bq[(cm >> 5) * 256 + head * 32 + (cm & 31)];
        float bv1 = bq[(cm >> 5) * 256 + head * 32 + (cm & 31) + 1];
        *(__half2*)(qk16 + r0 * QS + col) =
            __floats2half2_rn(acc[t][0] + bv0, acc[t][1] + bv1);
        *(__half2*)(qk16 + (r0 + 8) * QS + col) =
            __floats2half2_rn(acc[t][2] + bv0, acc[t][3] + bv1);
      }
      __syncthreads();

      // attention for 2 heads: one warp per sequence
      {
        const int bi = warp;
        const int qt = lane >> 3, kt = (lane >> 1) & 3, dh = lane & 1;
#pragma unroll
        for (int hh = 0; hh < 2; hh++) {
          const __half2* q2 = (const __half2*)(qk16 + (bi * 4 + qt) * QS + hh * 96 + dh * 16);
          const __half2* k2 = (const __half2*)(qk16 + (bi * 4 + kt) * QS + hh * 96 + 32 + dh * 16);
          const __half2* v2 = (const __half2*)(qk16 + (bi * 4 + kt) * QS + hh * 96 + 64 + dh * 16);
          float s = 0.f;
#pragma unroll
          for (int d = 0; d < 8; d++) {
            float2 qa = __half22float2(q2[d]), ka = __half22float2(k2[d]);
            s += qa.x * ka.x + qa.y * ka.y;
          }
          s += __shfl_xor_sync(0xffffffffu, s, 1);
          s *= 0.17677669529663687f;
          float mx = fmaxf(s, __shfl_xor_sync(0xffffffffu, s, 2));
          mx = fmaxf(mx, __shfl_xor_sync(0xffffffffu, mx, 4));
          float pr = expf(s - mx);
          float dn = pr + __shfl_xor_sync(0xffffffffu, pr, 2);
          dn += __shfl_xor_sync(0xffffffffu, dn, 4);
          pr /= dn;
          float pv[16];
#pragma unroll
          for (int d = 0; d < 8; d++) {
            float2 va = __half22float2(v2[d]);
            float x0 = pr * va.x, x1 = pr * va.y;
            x0 += __shfl_xor_sync(0xffffffffu, x0, 2);
            x1 += __shfl_xor_sync(0xffffffffu, x1, 2);
            x0 += __shfl_xor_sync(0xffffffffu, x0, 4);
            x1 += __shfl_xor_sync(0xffffffffu, x1, 4);
            pv[2 * d] = x0; pv[2 * d + 1] = x1;
          }
          if (kt == 0) {
            __half2* o2 = (__half2*)(oB + (bi * 4 + qt) * HS + (2 * p + hh) * 32 + dh * 16);
#pragma unroll
            for (int d = 0; d < 8; d++)
              o2[d] = __floats2half2_rn(pv[2 * d], pv[2 * d + 1]);
          }
        }
      }
      __syncthreads();
    }

    // ========== the three square GEMMs: warp 32x32, k-streamed ==========
    const int wr2 = warp >> 3, wc2 = warp & 7;
    const uint32_t bOff2 =
        (uint32_t)(((lane & 15) * WWS + wc2 * 32 + ((lane >> 4) << 3)) << 1);
#pragma unroll 1
    for (int gg = 0; gg < 3; gg++) {
      const __half* gw = (gg == 0)   ? g_Wo + (size_t)l * kD * kD
                         : (gg == 1) ? g_W1 + (size_t)l * kD * kD
                                     : g_W2 + (size_t)l * kD * kD;
      const uint32_t aBase = (gg == 1) ? hA_u : oB_u;
      load_chunk_w(wtU[0], gw, 0, tid);
      cp_commit();
      float acc[2][4][4];
#pragma unroll
      for (int t = 0; t < 2; t++)
#pragma unroll
        for (int i = 0; i < 4; i++)
#pragma unroll
          for (int j = 0; j < 4; j++) acc[t][i][j] = 0.f;
      uint32_t aA[2];
#pragma unroll
      for (int t = 0; t < 2; t++)
        aA[t] = aBase + (uint32_t)(((32 * wr2 + t * 16 + (lane & 15)) * HS +
                                    ((lane >> 4) << 3)) << 1);
      for (int c = 0; c < 4; c++) {
        if (c < 3) {
          load_chunk_w(wtU[(c + 1) & 1], gw, c + 1, tid);
          cp_commit();
          cp_wait<1>();
        } else {
          cp_wait<0>();
        }
        __syncthreads();
        const uint32_t bA = wtU[c & 1] + bOff2;
#pragma unroll
        for (int kl = 0; kl < 64; kl += 16) {
          uint32_t a[2][4];
#pragma unroll
          for (int t = 0; t < 2; t++)
            ldsm4(a[t][0], a[t][1], a[t][2], a[t][3],
                  aA[t] + (uint32_t)((c * 64 + kl) << 1));
          uint32_t b0, b1, b2, b3, c0, c1, c2, c3;
          ldsm4t(b0, b1, b2, b3, bA + (uint32_t)((kl * WWS) << 1));
          ldsm4t(c0, c1, c2, c3, bA + (uint32_t)((kl * WWS + 16) << 1));
#pragma unroll
          for (int t = 0; t < 2; t++) {
            mma16816(acc[t][0], a[t][0], a[t][1], a[t][2], a[t][3], b0, b1);
            mma16816(acc[t][1], a[t][0], a[t][1], a[t][2], a[t][3], b2, b3);
            mma16816(acc[t][2], a[t][0], a[t][1], a[t][2], a[t][3], c0, c1);
            mma16816(acc[t][3], a[t][0], a[t][1], a[t][2], a[t][3], c2, c3);
          }
        }
        __syncthreads();
      }
      // epilogues
      const int rb = 32 * wr2 + (lane >> 2);
      const int cl = 2 * (lane & 3);
      if (gg == 1) {  // GELU -> oB
        const float* bb = b1 + l * 256;
#pragma unroll
        for (int t = 0; t < 2; t++)
#pragma unroll
          for (int n = 0; n < 4; n++) {
            int col = wc2 * 32 + n * 8 + cl;
            float bv0 = bb[col], bv1 = bb[col + 1];
#pragma unroll
            for (int q = 0; q < 2; q++) {
              int row = rb + t * 16 + q * 8;
              float v0 = acc[t][n][2 * q] + bv0, v1 = acc[t][n][2 * q + 1] + bv1;
              *(__half2*)(oB + row * HS + col) = __floats2half2_rn(
                  0.5f * v0 * (1.0f + erff(v0 * 0.7071067811865475f)),
                  0.5f * v1 * (1.0f + erff(v1 * 0.7071067811865475f)));
            }
          }
      } else {  // residual add
        const float* bb = (gg == 0) ? bo + l * 256 : b2 + l * 256;
#pragma unroll
        for (int t = 0; t < 2; t++)
#pragma unroll
          for (int n = 0; n < 4; n++) {
            int col = wc2 * 32 + n * 8 + cl;
            float bv0 = bb[col], bv1 = bb[col + 1];
#pragma unroll
            for (int q = 0; q < 2; q++) {
              int row = rb + t * 16 + q * 8;
              xs[row * XSD + col] += acc[t][n][2 * q] + bv0;
              xs[row * XSD + col + 1] += acc[t][n][2 * q + 1] + bv1;
            }
          }
      }
      __syncthreads();
      if (gg == 0) {  // LN2 -> hA for W1
        ln_to_half(xs, hA, ln2_g + l * 256, ln2_b + l * 256, tid);
        __syncthreads();
      }
    }
  }

  // ---- final LN, mean over 4 tokens, output LN ----
  ln_inplace(xs, final_g, final_b, tid);
  __syncthreads();
  {
    int b = warp;
    const float* base = xs + b * 4 * XSD;
    float v[8], s = 0.f, s2 = 0.f;
#pragma unroll
    for (int j = 0; j < 8; j++) {
      int c = lane * 8 + j;
      float m = 0.25f * (base[c] + base[XSD + c] + base[2 * XSD + c] + base[3 * XSD + c]);
      v[j] = m; s += m; s2 += m * m;
    }
#pragma unroll
    for (int o = 16; o > 0; o >>= 1) {
      s += __shfl_xor_sync(0xffffffffu, s, o);
      s2 += __shfl_xor_sync(0xffffffffu, s2, o);
    }
    float mean = s * (1.f / 256.f);
    float rstd = rsqrtf(s2 * (1.f / 256.f) - mean * mean + 1e-5f);
#pragma unroll
    for (int j = 0; j < 8; j++) {
      int c = lane * 8 + j;
      out[(size_t)(gb0 + b) * 256 + c] = (v[j] - mean) * rstd * out_g[c] + out_b[c];
    }
  }
}

extern "C" void kernel_launch(void* const* d_in, const int* in_sizes, int n_in,
                              void* d_out, int out_size) {
  (void)in_sizes; (void)n_in; (void)out_size;
  const float* global_emb = (const float*)d_in[0];
  const float* pert_emb   = (const float*)d_in[1];
  const float* sym_feat   = (const float*)d_in[2];
  const float* ppi_feat   = (const float*)d_in[3];
  const float* sym_W      = (const float*)d_in[4];
  const float* sym_b      = (const float*)d_in[5];
  const float* sym_ln_g   = (const float*)d_in[6];
  const float* sym_ln_b   = (const float*)d_in[7];
  const float* tte        = (const float*)d_in[8];
  const float* Wqkv       = (const float*)d_in[9];
  const float* bqkv       = (const float*)d_in[10];
  const float* Wo         = (const float*)d_in[11];
  const float* bo         = (const float*)d_in[12];
  const float* ln1_g      = (const float*)d_in[13];
  const float* ln1_b      = (const float*)d_in[14];
  const float* ln2_g      = (const float*)d_in[15];
  const float* ln2_b      = (const float*)d_in[16];
  const float* W1         = (const float*)d_in[17];
  const float* b1         = (const float*)d_in[18];
  const float* W2         = (const float*)d_in[19];
  const float* b2         = (const float*)d_in[20];
  const float* final_g    = (const float*)d_in[21];
  const float* final_b    = (const float*)d_in[22];
  const float* out_g      = (const float*)d_in[23];
  const float* out_b      = (const float*)d_in[24];

  static bool attr_done = false;
  if (!attr_done) {
    cudaFuncSetAttribute(fused_kernel, cudaFuncAttributeMaxDynamicSharedMemorySize,
                         SMEM_BYTES);
    attr_done = true;
  }

  const int NTOT = kL * kD * 3 * kD + 3 * kL * kD * kD;
  prep_weights_kernel<<<(NTOT + 255) / 256, 256>>>(Wqkv, Wo, W1, W2);
  fused_kernel<<<kB / kMB, kNT, SMEM_BYTES>>>(
      global_emb, pert_emb, sym_feat, ppi_feat, sym_W, sym_b, sym_ln_g, sym_ln_b,
      tte, bqkv, bo, ln1_g, ln1_b, ln2_g, ln2_b, b1, b2, final_g, final_b, out_g,
      out_b, (float*)d_out);
}

// round 13
// speedup vs baseline: 1.4209x; 1.0120x over previous
#include <cuda_runtime.h>
#include <cuda_fp16.h>
#include <stdint.h>
#include <math.h>

#define kD 256
#define kH 8
#define kL 3
#define kB 32768
#define kMB 8
#define kNT 256
#define HS 264    // A-operand half stride
#define XSD 260   // xs float stride
#define QS 200    // qkv fp16 stride (2 heads)
#define WQS 216   // qkv weight-chunk half stride
#define WWS 264   // square weight-chunk half stride
#define CHK 32    // k-rows per weight chunk
#define NCH 8     // chunks per K=256

#define XO 0
#define HAO 33280
#define WOF 50176
#define WBUF 16896
#define QOF 83968
#define OOF 96768
#define SMEM_BYTES 113664

__device__ __align__(16) __half g_Wqkv[kL * kD * 3 * kD];
__device__ __align__(16) __half g_Wo[kL * kD * kD];
__device__ __align__(16) __half g_W1[kL * kD * kD];
__device__ __align__(16) __half g_W2[kL * kD * kD];

__global__ void prep_weights_kernel(const float* __restrict__ wqkv,
                                    const float* __restrict__ wo,
                                    const float* __restrict__ w1,
                                    const float* __restrict__ w2) {
  int i = blockIdx.x * blockDim.x + threadIdx.x;
  const int NQ = kL * kD * 3 * kD, NO = kL * kD * kD;
  if (i < NQ) { g_Wqkv[i] = __float2half_rn(wqkv[i]); return; }
  i -= NQ;
  if (i < NO) { g_Wo[i] = __float2half_rn(wo[i]); return; }
  i -= NO;
  if (i < NO) { g_W1[i] = __float2half_rn(w1[i]); return; }
  i -= NO;
  if (i < NO) { g_W2[i] = __float2half_rn(w2[i]); return; }
}

__device__ __forceinline__ uint32_t smem_u32(const void* p) {
  uint32_t a;
  asm volatile("{ .reg .u64 t; cvta.to.shared.u64 t, %1; cvt.u32.u64 %0, t; }"
               : "=r"(a) : "l"(p));
  return a;
}
__device__ __forceinline__ void ldsm4(uint32_t& r0, uint32_t& r1, uint32_t& r2,
                                      uint32_t& r3, uint32_t a) {
  asm volatile("ldmatrix.sync.aligned.m8n8.x4.shared.b16 {%0,%1,%2,%3}, [%4];"
               : "=r"(r0), "=r"(r1), "=r"(r2), "=r"(r3) : "r"(a));
}
__device__ __forceinline__ void ldsm4t(uint32_t& r0, uint32_t& r1, uint32_t& r2,
                                       uint32_t& r3, uint32_t a) {
  asm volatile("ldmatrix.sync.aligned.m8n8.x4.trans.shared.b16 {%0,%1,%2,%3}, [%4];"
               : "=r"(r0), "=r"(r1), "=r"(r2), "=r"(r3) : "r"(a));
}
__device__ __forceinline__ void ldsm2t(uint32_t& r0, uint32_t& r1, uint32_t a) {
  asm volatile("ldmatrix.sync.aligned.m8n8.x2.trans.shared.b16 {%0,%1}, [%2];"
               : "=r"(r0), "=r"(r1) : "r"(a));
}
__device__ __forceinline__ void mma16816(float* c, uint32_t a0, uint32_t a1,
                                         uint32_t a2, uint32_t a3, uint32_t b0,
                                         uint32_t b1) {
  asm volatile(
      "mma.sync.aligned.m16n8k16.row.col.f32.f16.f16.f32 "
      "{%0,%1,%2,%3}, {%4,%5,%6,%7}, {%8,%9}, {%0,%1,%2,%3};"
      : "+f"(c[0]), "+f"(c[1]), "+f"(c[2]), "+f"(c[3])
      : "r"(a0), "r"(a1), "r"(a2), "r"(a3), "r"(b0), "r"(b1));
}
__device__ __forceinline__ void cp16(uint32_t dst, const void* src) {
  asm volatile("cp.async.cg.shared.global [%0], [%1], 16;" :: "r"(dst), "l"(src));
}
__device__ __forceinline__ void cp_commit() { asm volatile("cp.async.commit_group;"); }
template <int N>
__device__ __forceinline__ void cp_wait() {
  asm volatile("cp.async.wait_group %0;" :: "n"(N));
}

__device__ __forceinline__ void row_stats(const float* __restrict__ row, int lane,
                                          float v[8], float& mean, float& rstd) {
  const float4* r4 = (const float4*)row;
  float4 a = r4[lane * 2], b = r4[lane * 2 + 1];
  v[0] = a.x; v[1] = a.y; v[2] = a.z; v[3] = a.w;
  v[4] = b.x; v[5] = b.y; v[6] = b.z; v[7] = b.w;
  float s = 0.f, s2 = 0.f;
#pragma unroll
  for (int j = 0; j < 8; j++) { s += v[j]; s2 += v[j] * v[j]; }
#pragma unroll
  for (int o = 16; o > 0; o >>= 1) {
    s += __shfl_xor_sync(0xffffffffu, s, o);
    s2 += __shfl_xor_sync(0xffffffffu, s2, o);
  }
  mean = s * (1.f / 256.f);
  rstd = rsqrtf(s2 * (1.f / 256.f) - mean * mean + 1e-5f);
}

__device__ __forceinline__ void ln_to_half(const float* __restrict__ xs,
                                           __half* __restrict__ dst,
                                           const float* __restrict__ g,
                                           const float* __restrict__ bt, int tid) {
  int warp = tid >> 5, lane = tid & 31;
#pragma unroll
  for (int i = 0; i < 4; i++) {
    int r = warp * 4 + i;
    float v[8], mean, rstd;
    row_stats(xs + r * XSD, lane, v, mean, rstd);
    __half2* d2 = (__half2*)(dst + r * HS + lane * 8);
#pragma unroll
    for (int j = 0; j < 4; j++) {
      int c = lane * 8 + 2 * j;
      d2[j] = __floats2half2_rn((v[2 * j] - mean) * rstd * g[c] + bt[c],
                                (v[2 * j + 1] - mean) * rstd * g[c + 1] + bt[c + 1]);
    }
  }
}

__device__ __forceinline__ void ln_inplace(float* __restrict__ xs,
                                           const float* __restrict__ g,
                                           const float* __restrict__ bt, int tid) {
  int warp = tid >> 5, lane = tid & 31;
#pragma unroll
  for (int i = 0; i < 4; i++) {
    int r = warp * 4 + i;
    float v[8], mean, rstd;
    row_stats(xs + r * XSD, lane, v, mean, rstd);
#pragma unroll
    for (int j = 0; j < 8; j++) {
      int c = lane * 8 + j;
      xs[r * XSD + c] = (v[j] - mean) * rstd * g[c] + bt[c];
    }
  }
}

// chunk c (32 k-rows) of square W[256][256] -> buf (stride WWS). 1024 cp16.
__device__ __forceinline__ void load_chunk_w(uint32_t buf, const __half* __restrict__ gw,
                                             int c, int tid) {
#pragma unroll
  for (int i = 0; i < 4; i++) {
    int u = tid + kNT * i;
    int r = u >> 5, s = u & 31;
    cp16(buf + (uint32_t)((r * WWS + s * 8) << 1),
         gw + (size_t)(c * CHK + r) * 256 + s * 8);
  }
}
// chunk c of gathered QKV head-pair p: 192 cols (stride WQS). 768 cp16.
__device__ __forceinline__ void load_chunk_qkv(uint32_t buf, const __half* __restrict__ gw,
                                               int p, int c, int tid) {
#pragma unroll
  for (int i = 0; i < 3; i++) {
    int u = tid + kNT * i;       // 0..767
    int r = u / 24, j = u - r * 24;
    int hp = j / 12, jm = j % 12, part = jm >> 2, sub = jm & 3;
    cp16(buf + (uint32_t)((r * WQS + j * 8) << 1),
         gw + (size_t)(c * CHK + r) * 768 + part * 256 + (2 * p + hp) * 32 + sub * 8);
  }
}

__global__ void __launch_bounds__(kNT, 2) fused_kernel(
    const float* __restrict__ global_emb, const float* __restrict__ pert_emb,
    const float* __restrict__ sym_feat, const float* __restrict__ ppi_feat,
    const float* __restrict__ sym_W, const float* __restrict__ sym_b,
    const float* __restrict__ sym_ln_g, const float* __restrict__ sym_ln_b,
    const float* __restrict__ tte, const float* __restrict__ bqkv,
    const float* __restrict__ bo, const float* __restrict__ ln1_g,
    const float* __restrict__ ln1_b, const float* __restrict__ ln2_g,
    const float* __restrict__ ln2_b, const float* __restrict__ b1,
    const float* __restrict__ b2, const float* __restrict__ final_g,
    const float* __restrict__ final_b, const float* __restrict__ out_g,
    const float* __restrict__ out_b, float* __restrict__ out) {
  extern __shared__ char smem[];
  float* xs = (float*)(smem + XO);
  __half* hA = (__half*)(smem + HAO);
  __half* qk16 = (__half*)(smem + QOF);
  __half* oB = (__half*)(smem + OOF);

  const int tid = threadIdx.x, warp = tid >> 5, lane = tid & 31;
  const int gb0 = blockIdx.x * kMB;
  const uint32_t hA_u = smem_u32(hA), oB_u = smem_u32(oB);
  const uint32_t wtU[2] = {smem_u32(smem + WOF), smem_u32(smem + WOF) + WBUF};

  // ---- initial x: tokens 0,1,3 + tte; stage sym_feat ----
#pragma unroll
  for (int i = 0; i < 8; i++) {
    int u = tid + kNT * i;      // 0..2047
    int b = u >> 8, c = u & 255;
    xs[(b * 4 + 0) * XSD + c] = global_emb[(size_t)(gb0 + b) * 256 + c] + tte[c];
    xs[(b * 4 + 1) * XSD + c] = pert_emb[(size_t)(gb0 + b) * 256 + c] + tte[256 + c];
    xs[(b * 4 + 3) * XSD + c] = ppi_feat[(size_t)(gb0 + b) * 256 + c] + tte[768 + c];
  }
  {
    float* stage = (float*)qk16;
#pragma unroll
    for (int i = 0; i < 2; i++) {
      int u = tid + kNT * i;    // 0..511
      stage[u] = sym_feat[(size_t)gb0 * 64 + u];
    }
  }
  __syncthreads();
  {  // sym projection fp32
    const float* stage = (const float*)qk16;
#pragma unroll
    for (int i = 0; i < 8; i++) {
      int u = tid + kNT * i;
      int b = u >> 8, c = u & 255;
      const float* sf = stage + b * 64;
      float acc = sym_b[c];
#pragma unroll 8
      for (int k = 0; k < 64; k++) acc += sf[k] * sym_W[k * 256 + c];
      xs[(b * 4 + 2) * XSD + c] = acc;
    }
  }
  __syncthreads();
  {  // sym LN + tte (1 seq per warp)
    int r = warp * 4 + 2;
    float v[8], mean, rstd;
    row_stats(xs + r * XSD, lane, v, mean, rstd);
#pragma unroll
    for (int j = 0; j < 8; j++) {
      int c = lane * 8 + j;
      xs[r * XSD + c] = (v[j] - mean) * rstd * sym_ln_g[c] + sym_ln_b[c] + tte[512 + c];
    }
  }
  __syncthreads();

  const int rb = lane >> 2;          // 0..7
  const int cl = 2 * (lane & 3);

  for (int l = 0; l < kL; l++) {
    ln_to_half(xs, hA, ln1_g + l * 256, ln1_b + l * 256, tid);
    __syncthreads();

    // ================= QKV: 4 head-pairs, warp tile 32x24 =================
    const __half* wq = g_Wqkv + (size_t)l * kD * 768;
    for (int p = 0; p < 4; p++) {
      load_chunk_qkv(wtU[0], wq, p, 0, tid);
      cp_commit();
      float acc[2][3][4];
#pragma unroll
      for (int t = 0; t < 2; t++)
#pragma unroll
        for (int n = 0; n < 3; n++)
#pragma unroll
          for (int j = 0; j < 4; j++) acc[t][n][j] = 0.f;
      uint32_t aA[2];
#pragma unroll
      for (int t = 0; t < 2; t++)
        aA[t] = hA_u + (uint32_t)(((t * 16 + (lane & 15)) * HS + ((lane >> 4) << 3)) << 1);
      const uint32_t bOff =
          (uint32_t)(((lane & 15) * WQS + warp * 24 + ((lane >> 4) << 3)) << 1);
      const uint32_t bOff2 = (uint32_t)(((lane & 15) * WQS + warp * 24 + 16) << 1);
      for (int c = 0; c < NCH; c++) {
        if (c < NCH - 1) {
          load_chunk_qkv(wtU[(c + 1) & 1], wq, p, c + 1, tid);
          cp_commit();
          cp_wait<1>();
        } else {
          cp_wait<0>();
        }
        __syncthreads();
        const uint32_t bB = wtU[c & 1];
#pragma unroll
        for (int kl = 0; kl < CHK; kl += 16) {
          uint32_t a[2][4];
#pragma unroll
          for (int t = 0; t < 2; t++)
            ldsm4(a[t][0], a[t][1], a[t][2], a[t][3],
                  aA[t] + (uint32_t)((c * CHK + kl) << 1));
          uint32_t b0, b1, b2, b3, c0, c1;
          ldsm4t(b0, b1, b2, b3, bB + bOff + (uint32_t)((kl * WQS) << 1));
          ldsm2t(c0, c1, bB + bOff2 + (uint32_t)((kl * WQS) << 1));
#pragma unroll
          for (int t = 0; t < 2; t++) {
            mma16816(acc[t][0], a[t][0], a[t][1], a[t][2], a[t][3], b0, b1);
            mma16816(acc[t][1], a[t][0], a[t][1], a[t][2], a[t][3], b2, b3);
            mma16816(acc[t][2], a[t][0], a[t][1], a[t][2], a[t][3], c0, c1);
          }
        }
        __syncthreads();
      }
      // epilogue -> qk16 fp16 (+bias)
      const float* bq = bqkv + l * 768;
#pragma unroll
      for (int t = 0; t < 2; t++)
#pragma unroll
        for (int n = 0; n < 3; n++) {
          int col = warp * 24 + n * 8 + cl;            // 0..191, even
          int head = 2 * p + (col >= 96), cm = col % 96;
          float bv0 = bq[(cm >> 5) * 256 + head * 32 + (cm & 31)];
          float bv1 = bq[(cm >> 5) * 256 + head * 32 + (cm & 31) + 1];
          int row = t * 16 + rb;
          *(__half2*)(qk16 + row * QS + col) =
              __floats2half2_rn(acc[t][n][0] + bv0, acc[t][n][1] + bv1);
          *(__half2*)(qk16 + (row + 8) * QS + col) =
              __floats2half2_rn(acc[t][n][2] + bv0, acc[t][n][3] + bv1);
        }
      __syncthreads();

      // attention for 2 heads: one warp per sequence
      {
        const int bi = warp;
        const int qt = lane >> 3, kt = (lane >> 1) & 3, dh = lane & 1;
#pragma unroll
        for (int hh = 0; hh < 2; hh++) {
          const __half2* q2 = (const __half2*)(qk16 + (bi * 4 + qt) * QS + hh * 96 + dh * 16);
          const __half2* k2 = (const __half2*)(qk16 + (bi * 4 + kt) * QS + hh * 96 + 32 + dh * 16);
          const __half2* v2 = (const __half2*)(qk16 + (bi * 4 + kt) * QS + hh * 96 + 64 + dh * 16);
          float s = 0.f;
#pragma unroll
          for (int d = 0; d < 8; d++) {
            float2 qa = __half22float2(q2[d]), ka = __half22float2(k2[d]);
            s += qa.x * ka.x + qa.y * ka.y;
          }
          s += __shfl_xor_sync(0xffffffffu, s, 1);
          s *= 0.17677669529663687f;
          float mx = fmaxf(s, __shfl_xor_sync(0xffffffffu, s, 2));
          mx = fmaxf(mx, __shfl_xor_sync(0xffffffffu, mx, 4));
          float pr = expf(s - mx);
          float dn = pr + __shfl_xor_sync(0xffffffffu, pr, 2);
          dn += __shfl_xor_sync(0xffffffffu, dn, 4);
          pr /= dn;
          float pv[16];
#pragma unroll
          for (int d = 0; d < 8; d++) {
            float2 va = __half22float2(v2[d]);
            float x0 = pr * va.x, x1 = pr * va.y;
            x0 += __shfl_xor_sync(0xffffffffu, x0, 2);
            x1 += __shfl_xor_sync(0xffffffffu, x1, 2);
            x0 += __shfl_xor_sync(0xffffffffu, x0, 4);
            x1 += __shfl_xor_sync(0xffffffffu, x1, 4);
            pv[2 * d] = x0; pv[2 * d + 1] = x1;
          }
          if (kt == 0) {
            __half2* o2 = (__half2*)(oB + (bi * 4 + qt) * HS + (2 * p + hh) * 32 + dh * 16);
#pragma unroll
            for (int d = 0; d < 8; d++)
              o2[d] = __floats2half2_rn(pv[2 * d], pv[2 * d + 1]);
          }
        }
      }
      __syncthreads();
    }

    // ========== square GEMMs: warp tile 32x32, k-streamed ==========
    const uint32_t bOffW =
        (uint32_t)(((lane & 15) * WWS + warp * 32 + ((lane >> 4) << 3)) << 1);
#pragma unroll 1
    for (int gg = 0; gg < 3; gg++) {
      const __half* gw = (gg == 0)   ? g_Wo + (size_t)l * kD * kD
                         : (gg == 1) ? g_W1 + (size_t)l * kD * kD
                                     : g_W2 + (size_t)l * kD * kD;
      const uint32_t aBase = (gg == 1) ? hA_u : oB_u;
      load_chunk_w(wtU[0], gw, 0, tid);
      cp_commit();
      float acc[2][4][4];
#pragma unroll
      for (int t = 0; t < 2; t++)
#pragma unroll
        for (int i = 0; i < 4; i++)
#pragma unroll
          for (int j = 0; j < 4; j++) acc[t][i][j] = 0.f;
      uint32_t aA[2];
#pragma unroll
      for (int t = 0; t < 2; t++)
        aA[t] = aBase + (uint32_t)(((t * 16 + (lane & 15)) * HS + ((lane >> 4) << 3)) << 1);
      for (int c = 0; c < NCH; c++) {
        if (c < NCH - 1) {
          load_chunk_w(wtU[(c + 1) & 1], gw, c + 1, tid);
          cp_commit();
          cp_wait<1>();
        } else {
          cp_wait<0>();
        }
        __syncthreads();
        const uint32_t bA = wtU[c & 1] + bOffW;
#pragma unroll
        for (int kl = 0; kl < CHK; kl += 16) {
          uint32_t a[2][4];
#pragma unroll
          for (int t = 0; t < 2; t++)
            ldsm4(a[t][0], a[t][1], a[t][2], a[t][3],
                  aA[t] + (uint32_t)((c * CHK + kl) << 1));
          uint32_t b0, b1, b2, b3, c0, c1, c2, c3;
          ldsm4t(b0, b1, b2, b3, bA + (uint32_t)((kl * WWS) << 1));
          ldsm4t(c0, c1, c2, c3, bA + (uint32_t)((kl * WWS + 16) << 1));
#pragma unroll
          for (int t = 0; t < 2; t++) {
            mma16816(acc[t][0], a[t][0], a[t][1], a[t][2], a[t][3], b0, b1);
            mma16816(acc[t][1], a[t][0], a[t][1], a[t][2], a[t][3], b2, b3);
            mma16816(acc[t][2], a[t][0], a[t][1], a[t][2], a[t][3], c0, c1);
            mma16816(acc[t][3], a[t][0], a[t][1], a[t][2], a[t][3], c2, c3);
          }
        }
        __syncthreads();
      }
      // epilogues
      if (gg == 1) {  // GELU -> oB
        const float* bb = b1 + l * 256;
#pragma unroll
        for (int t = 0; t < 2; t++)
#pragma unroll
          for (int n = 0; n < 4; n++) {
            int col = warp * 32 + n * 8 + cl;
            float bv0 = bb[col], bv1 = bb[col + 1];
#pragma unroll
            for (int q = 0; q < 2; q++) {
              int row = t * 16 + q * 8 + rb;
              float v0 = acc[t][n][2 * q] + bv0, v1 = acc[t][n][2 * q + 1] + bv1;
              *(__half2*)(oB + row * HS + col) = __floats2half2_rn(
                  0.5f * v0 * (1.0f + erff(v0 * 0.7071067811865475f)),
                  0.5f * v1 * (1.0f + erff(v1 * 0.7071067811865475f)));
            }
          }
      } else {  // residual add
        const float* bb = (gg == 0) ? bo + l * 256 : b2 + l * 256;
#pragma unroll
        for (int t = 0; t < 2; t++)
#pragma unroll
          for (int n = 0; n < 4; n++) {
            int col = warp * 32 + n * 8 + cl;
            float bv0 = bb[col], bv1 = bb[col + 1];
#pragma unroll
            for (int q = 0; q < 2; q++) {
              int row = t * 16 + q * 8 + rb;
              xs[row * XSD + col] += acc[t][n][2 * q] + bv0;
              xs[row * XSD + col + 1] += acc[t][n][2 * q + 1] + bv1;
            }
          }
      }
      __syncthreads();
      if (gg == 0) {  // LN2 -> hA for W1
        ln_to_half(xs, hA, ln2_g + l * 256, ln2_b + l * 256, tid);
        __syncthreads();
      }
    }
  }

  // ---- final LN, mean over 4 tokens, output LN ----
  ln_inplace(xs, final_g, final_b, tid);
  __syncthreads();
  {
    int b = warp;
    const float* base = xs + b * 4 * XSD;
    float v[8], s = 0.f, s2 = 0.f;
#pragma unroll
    for (int j = 0; j < 8; j++) {
      int c = lane * 8 + j;
      float m = 0.25f * (base[c] + base[XSD + c] + base[2 * XSD + c] + base[3 * XSD + c]);
      v[j] = m; s += m; s2 += m * m;
    }
#pragma unroll
    for (int o = 16; o > 0; o >>= 1) {
      s += __shfl_xor_sync(0xffffffffu, s, o);
      s2 += __shfl_xor_sync(0xffffffffu, s2, o);
    }
    float mean = s * (1.f / 256.f);
    float rstd = rsqrtf(s2 * (1.f / 256.f) - mean * mean + 1e-5f);
#pragma unroll
    for (int j = 0; j < 8; j++) {
      int c = lane * 8 + j;
      out[(size_t)(gb0 + b) * 256 + c] = (v[j] - mean) * rstd * out_g[c] + out_b[c];
    }
  }
}

extern "C" void kernel_launch(void* const* d_in, const int* in_sizes, int n_in,
                              void* d_out, int out_size) {
  (void)in_sizes; (void)n_in; (void)out_size;
  const float* global_emb = (const float*)d_in[0];
  const float* pert_emb   = (const float*)d_in[1];
  const float* sym_feat   = (const float*)d_in[2];
  const float* ppi_feat   = (const float*)d_in[3];
  const float* sym_W      = (const float*)d_in[4];
  const float* sym_b      = (const float*)d_in[5];
  const float* sym_ln_g   = (const float*)d_in[6];
  const float* sym_ln_b   = (const float*)d_in[7];
  const float* tte        = (const float*)d_in[8];
  const float* Wqkv       = (const float*)d_in[9];
  const float* bqkv       = (const float*)d_in[10];
  const float* Wo         = (const float*)d_in[11];
  const float* bo         = (const float*)d_in[12];
  const float* ln1_g      = (const float*)d_in[13];
  const float* ln1_b      = (const float*)d_in[14];
  const float* ln2_g      = (const float*)d_in[15];
  const float* ln2_b      = (const float*)d_in[16];
  const float* W1         = (const float*)d_in[17];
  const float* b1         = (const float*)d_in[18];
  const float* W2         = (const float*)d_in[19];
  const float* b2         = (const float*)d_in[20];
  const float* final_g    = (const float*)d_in[21];
  const float* final_b    = (const float*)d_in[22];
  const float* out_g      = (const float*)d_in[23];
  const float* out_b      = (const float*)d_in[24];

  static bool attr_done = false;
  if (!attr_done) {
    cudaFuncSetAttribute(fused_kernel, cudaFuncAttributeMaxDynamicSharedMemorySize,
                         SMEM_BYTES);
    attr_done = true;
  }

  const int NTOT = kL * kD * 3 * kD + 3 * kL * kD * kD;
  prep_weights_kernel<<<(NTOT + 255) / 256, 256>>>(Wqkv, Wo, W1, W2);
  fused_kernel<<<kB / kMB, kNT, SMEM_BYTES>>>(
      global_emb, pert_emb, sym_feat, ppi_feat, sym_W, sym_b, sym_ln_g, sym_ln_b,
      tte, bqkv, bo, ln1_g, ln1_b, ln2_g, ln2_b, b1, b2, final_g, final_b, out_g,
      out_b, (float*)d_out);
}

// round 14
// speedup vs baseline: 1.4261x; 1.0037x over previous
#include <cuda_runtime.h>
#include <cuda_fp16.h>
#include <stdint.h>
#include <math.h>

#define kD 256
#define kH 8
#define kL 3
#define kB 32768
#define kMB 8
#define kNT 256
#define HS 264    // A-operand half stride
#define XSD 260   // xs float stride
#define QS 200    // qkv fp16 stride (2 heads)
#define WBS 40    // per-warp B-slice stride (halves)
#define CHK 16    // k-rows per chunk
#define NCH 16    // chunks per K=256
#define WB_CHUNK (CHK * WBS * 2)      // 1280 B
#define WB_PER_WARP (3 * WB_CHUNK)    // 3840 B

#define XO 0
#define HAO 33280
#define WOF 50176
#define QOF 80896
#define OOF 93696
#define SMEM_BYTES 110592

__device__ __align__(16) __half g_Wqkv[kL * kD * 3 * kD];
__device__ __align__(16) __half g_Wo[kL * kD * kD];
__device__ __align__(16) __half g_W1[kL * kD * kD];
__device__ __align__(16) __half g_W2[kL * kD * kD];

__global__ void prep_weights_kernel(const float* __restrict__ wqkv,
                                    const float* __restrict__ wo,
                                    const float* __restrict__ w1,
                                    const float* __restrict__ w2) {
  int i = blockIdx.x * blockDim.x + threadIdx.x;
  const int NQ = kL * kD * 3 * kD, NO = kL * kD * kD;
  if (i < NQ) { g_Wqkv[i] = __float2half_rn(wqkv[i]); return; }
  i -= NQ;
  if (i < NO) { g_Wo[i] = __float2half_rn(wo[i]); return; }
  i -= NO;
  if (i < NO) { g_W1[i] = __float2half_rn(w1[i]); return; }
  i -= NO;
  if (i < NO) { g_W2[i] = __float2half_rn(w2[i]); return; }
}

__device__ __forceinline__ uint32_t smem_u32(const void* p) {
  uint32_t a;
  asm volatile("{ .reg .u64 t; cvta.to.shared.u64 t, %1; cvt.u32.u64 %0, t; }"
               : "=r"(a) : "l"(p));
  return a;
}
__device__ __forceinline__ void ldsm4(uint32_t& r0, uint32_t& r1, uint32_t& r2,
                                      uint32_t& r3, uint32_t a) {
  asm volatile("ldmatrix.sync.aligned.m8n8.x4.shared.b16 {%0,%1,%2,%3}, [%4];"
               : "=r"(r0), "=r"(r1), "=r"(r2), "=r"(r3) : "r"(a));
}
__device__ __forceinline__ void ldsm4t(uint32_t& r0, uint32_t& r1, uint32_t& r2,
                                       uint32_t& r3, uint32_t a) {
  asm volatile("ldmatrix.sync.aligned.m8n8.x4.trans.shared.b16 {%0,%1,%2,%3}, [%4];"
               : "=r"(r0), "=r"(r1), "=r"(r2), "=r"(r3) : "r"(a));
}
__device__ __forceinline__ void ldsm2t(uint32_t& r0, uint32_t& r1, uint32_t a) {
  asm volatile("ldmatrix.sync.aligned.m8n8.x2.trans.shared.b16 {%0,%1}, [%2];"
               : "=r"(r0), "=r"(r1) : "r"(a));
}
__device__ __forceinline__ void mma16816(float* c, uint32_t a0, uint32_t a1,
                                         uint32_t a2, uint32_t a3, uint32_t b0,
                                         uint32_t b1) {
  asm volatile(
      "mma.sync.aligned.m16n8k16.row.col.f32.f16.f16.f32 "
      "{%0,%1,%2,%3}, {%4,%5,%6,%7}, {%8,%9}, {%0,%1,%2,%3};"
      : "+f"(c[0]), "+f"(c[1]), "+f"(c[2]), "+f"(c[3])
      : "r"(a0), "r"(a1), "r"(a2), "r"(a3), "r"(b0), "r"(b1));
}
__device__ __forceinline__ void cp16(uint32_t dst, const void* src) {
  asm volatile("cp.async.cg.shared.global [%0], [%1], 16;" :: "r"(dst), "l"(src));
}
__device__ __forceinline__ void cp_commit() { asm volatile("cp.async.commit_group;"); }
template <int N>
__device__ __forceinline__ void cp_wait() {
  asm volatile("cp.async.wait_group %0;" :: "n"(N));
}

__device__ __forceinline__ void row_stats(const float* __restrict__ row, int lane,
                                          float v[8], float& mean, float& rstd) {
  const float4* r4 = (const float4*)row;
  float4 a = r4[lane * 2], b = r4[lane * 2 + 1];
  v[0] = a.x; v[1] = a.y; v[2] = a.z; v[3] = a.w;
  v[4] = b.x; v[5] = b.y; v[6] = b.z; v[7] = b.w;
  float s = 0.f, s2 = 0.f;
#pragma unroll
  for (int j = 0; j < 8; j++) { s += v[j]; s2 += v[j] * v[j]; }
#pragma unroll
  for (int o = 16; o > 0; o >>= 1) {
    s += __shfl_xor_sync(0xffffffffu, s, o);
    s2 += __shfl_xor_sync(0xffffffffu, s2, o);
  }
  mean = s * (1.f / 256.f);
  rstd = rsqrtf(s2 * (1.f / 256.f) - mean * mean + 1e-5f);
}

__device__ __forceinline__ void ln_to_half(const float* __restrict__ xs,
                                           __half* __restrict__ dst,
                                           const float* __restrict__ g,
                                           const float* __restrict__ bt, int tid) {
  int warp = tid >> 5, lane = tid & 31;
#pragma unroll
  for (int i = 0; i < 4; i++) {
    int r = warp * 4 + i;
    float v[8], mean, rstd;
    row_stats(xs + r * XSD, lane, v, mean, rstd);
    __half2* d2 = (__half2*)(dst + r * HS + lane * 8);
#pragma unroll
    for (int j = 0; j < 4; j++) {
      int c = lane * 8 + 2 * j;
      d2[j] = __floats2half2_rn((v[2 * j] - mean) * rstd * g[c] + bt[c],
                                (v[2 * j + 1] - mean) * rstd * g[c + 1] + bt[c + 1]);
    }
  }
}

__device__ __forceinline__ void ln_inplace(float* __restrict__ xs,
                                           const float* __restrict__ g,
                                           const float* __restrict__ bt, int tid) {
  int warp = tid >> 5, lane = tid & 31;
#pragma unroll
  for (int i = 0; i < 4; i++) {
    int r = warp * 4 + i;
    float v[8], mean, rstd;
    row_stats(xs + r * XSD, lane, v, mean, rstd);
#pragma unroll
    for (int j = 0; j < 8; j++) {
      int c = lane * 8 + j;
      xs[r * XSD + c] = (v[j] - mean) * rstd * g[c] + bt[c];
    }
  }
}

// per-warp chunk loaders: each warp fills its OWN buffer (no block sync needed)
__device__ __forceinline__ void load_w_warp(uint32_t buf, const __half* __restrict__ gw,
                                            int c, int col0, int lane) {
#pragma unroll
  for (int i = 0; i < 2; i++) {
    int u = lane + 32 * i;          // 0..63
    int r = u >> 2, s = u & 3;      // 16 rows x 4 groups
    cp16(buf + (uint32_t)((r * WBS + s * 8) << 1),
         gw + (size_t)(c * CHK + r) * 256 + col0 + s * 8);
  }
}
__device__ __forceinline__ void load_qkv_warp(uint32_t buf, const __half* __restrict__ gw,
                                              const int* goff, int c, int lane) {
#pragma unroll
  for (int i = 0; i < 2; i++) {
    int u = lane + 32 * i;          // 0..63, use 0..47
    if (u < 48) {
      int r = u / 3, g = u - 3 * (u / 3);
      cp16(buf + (uint32_t)((r * WBS + g * 8) << 1),
           gw + (size_t)(c * CHK + r) * 768 + goff[g]);
    }
  }
}

__global__ void __launch_bounds__(kNT, 2) fused_kernel(
    const float* __restrict__ global_emb, const float* __restrict__ pert_emb,
    const float* __restrict__ sym_feat, const float* __restrict__ ppi_feat,
    const float* __restrict__ sym_W, const float* __restrict__ sym_b,
    const float* __restrict__ sym_ln_g, const float* __restrict__ sym_ln_b,
    const float* __restrict__ tte, const float* __restrict__ bqkv,
    const float* __restrict__ bo, const float* __restrict__ ln1_g,
    const float* __restrict__ ln1_b, const float* __restrict__ ln2_g,
    const float* __restrict__ ln2_b, const float* __restrict__ b1,
    const float* __restrict__ b2, const float* __restrict__ final_g,
    const float* __restrict__ final_b, const float* __restrict__ out_g,
    const float* __restrict__ out_b, float* __restrict__ out) {
  extern __shared__ char smem[];
  float* xs = (float*)(smem + XO);
  __half* hA = (__half*)(smem + HAO);
  __half* qk16 = (__half*)(smem + QOF);
  __half* oB = (__half*)(smem + OOF);

  const int tid = threadIdx.x, warp = tid >> 5, lane = tid & 31;
  const int gb0 = blockIdx.x * kMB;
  const uint32_t hA_u = smem_u32(hA), oB_u = smem_u32(oB);
  const uint32_t wbBase = smem_u32(smem + WOF) + warp * WB_PER_WARP;

  // ---- initial x: tokens 0,1,3 + tte; stage sym_feat ----
#pragma unroll
  for (int i = 0; i < 8; i++) {
    int u = tid + kNT * i;
    int b = u >> 8, c = u & 255;
    xs[(b * 4 + 0) * XSD + c] = global_emb[(size_t)(gb0 + b) * 256 + c] + tte[c];
    xs[(b * 4 + 1) * XSD + c] = pert_emb[(size_t)(gb0 + b) * 256 + c] + tte[256 + c];
    xs[(b * 4 + 3) * XSD + c] = ppi_feat[(size_t)(gb0 + b) * 256 + c] + tte[768 + c];
  }
  {
    float* stage = (float*)qk16;
#pragma unroll
    for (int i = 0; i < 2; i++) {
      int u = tid + kNT * i;
      stage[u] = sym_feat[(size_t)gb0 * 64 + u];
    }
  }
  __syncthreads();
  {  // sym projection fp32
    const float* stage = (const float*)qk16;
#pragma unroll
    for (int i = 0; i < 8; i++) {
      int u = tid + kNT * i;
      int b = u >> 8, c = u & 255;
      const float* sf = stage + b * 64;
      float acc = sym_b[c];
#pragma unroll 8
      for (int k = 0; k < 64; k++) acc += sf[k] * sym_W[k * 256 + c];
      xs[(b * 4 + 2) * XSD + c] = acc;
    }
  }
  __syncthreads();
  {  // sym LN + tte
    int r = warp * 4 + 2;
    float v[8], mean, rstd;
    row_stats(xs + r * XSD, lane, v, mean, rstd);
#pragma unroll
    for (int j = 0; j < 8; j++) {
      int c = lane * 8 + j;
      xs[r * XSD + c] = (v[j] - mean) * rstd * sym_ln_g[c] + sym_ln_b[c] + tte[512 + c];
    }
  }
  __syncthreads();

  const int rb = lane >> 2;
  const int cl = 2 * (lane & 3);
  // gathered-QKV gmem offsets for this warp's 3 col-groups (head index added per phase)
  int gbase[3], ghp[3];
#pragma unroll
  for (int g = 0; g < 3; g++) {
    int col = warp * 24 + g * 8;
    ghp[g] = col / 96;
    int rem = col - ghp[g] * 96;
    gbase[g] = (rem >> 5) * 256 + (rem & 31);
  }
  uint32_t aA[2];
#pragma unroll
  for (int t = 0; t < 2; t++)
    aA[t] = (uint32_t)(((t * 16 + (lane & 15)) * HS + ((lane >> 4) << 3)) << 1);
  const uint32_t bOff = (uint32_t)(((lane & 15) * WBS + ((lane >> 4) << 3)) << 1);
  const uint32_t bOff2 = (uint32_t)(((lane & 15) * WBS + 16) << 1);

  for (int l = 0; l < kL; l++) {
    ln_to_half(xs, hA, ln1_g + l * 256, ln1_b + l * 256, tid);
    __syncthreads();

    // ================= QKV: 4 head-pair phases, barrier-free mainloop ======
    const __half* wq = g_Wqkv + (size_t)l * kD * 768;
    for (int p = 0; p < 4; p++) {
      int goff[3];
#pragma unroll
      for (int g = 0; g < 3; g++) goff[g] = gbase[g] + (2 * p + ghp[g]) * 32;
      load_qkv_warp(wbBase, wq, goff, 0, lane);
      cp_commit();
      load_qkv_warp(wbBase + WB_CHUNK, wq, goff, 1, lane);
      cp_commit();
      float acc[2][3][4];
#pragma unroll
      for (int t = 0; t < 2; t++)
#pragma unroll
        for (int n = 0; n < 3; n++)
#pragma unroll
          for (int j = 0; j < 4; j++) acc[t][n][j] = 0.f;
#pragma unroll 4
      for (int c = 0; c < NCH; c++) {
        if (c + 2 < NCH)
          load_qkv_warp(wbBase + ((c + 2) % 3) * WB_CHUNK, wq, goff, c + 2, lane);
        cp_commit();
        cp_wait<2>();
        __syncwarp();
        const uint32_t bA = wbBase + (c % 3) * WB_CHUNK;
        uint32_t a[2][4];
#pragma unroll
        for (int t = 0; t < 2; t++)
          ldsm4(a[t][0], a[t][1], a[t][2], a[t][3],
                hA_u + aA[t] + (uint32_t)((c * CHK) << 1));
        uint32_t b0, b1, b2, b3, c0, c1;
        ldsm4t(b0, b1, b2, b3, bA + bOff);
        ldsm2t(c0, c1, bA + bOff2);
#pragma unroll
        for (int t = 0; t < 2; t++) {
          mma16816(acc[t][0], a[t][0], a[t][1], a[t][2], a[t][3], b0, b1);
          mma16816(acc[t][1], a[t][0], a[t][1], a[t][2], a[t][3], b2, b3);
          mma16816(acc[t][2], a[t][0], a[t][1], a[t][2], a[t][3], c0, c1);
        }
      }
      // epilogue -> qk16 fp16 (+bias)
      const float* bq = bqkv + l * 768;
#pragma unroll
      for (int t = 0; t < 2; t++)
#pragma unroll
        for (int n = 0; n < 3; n++) {
          int col = warp * 24 + n * 8 + cl;            // 0..191
          int head = 2 * p + (col >= 96), cm = col % 96;
          float bv0 = bq[(cm >> 5) * 256 + head * 32 + (cm & 31)];
          float bv1 = bq[(cm >> 5) * 256 + head * 32 + (cm & 31) + 1];
          int row = t * 16 + rb;
          *(__half2*)(qk16 + row * QS + col) =
              __floats2half2_rn(acc[t][n][0] + bv0, acc[t][n][1] + bv1);
          *(__half2*)(qk16 + (row + 8) * QS + col) =
              __floats2half2_rn(acc[t][n][2] + bv0, acc[t][n][3] + bv1);
        }
      __syncthreads();

      // attention for 2 heads: one warp per sequence
      {
        const int bi = warp;
        const int qt = lane >> 3, kt = (lane >> 1) & 3, dh = lane & 1;
#pragma unroll
        for (int hh = 0; hh < 2; hh++) {
          const __half2* q2 = (const __half2*)(qk16 + (bi * 4 + qt) * QS + hh * 96 + dh * 16);
          const __half2* k2 = (const __half2*)(qk16 + (bi * 4 + kt) * QS + hh * 96 + 32 + dh * 16);
          const __half2* v2 = (const __half2*)(qk16 + (bi * 4 + kt) * QS + hh * 96 + 64 + dh * 16);
          float s = 0.f;
#pragma unroll
          for (int d = 0; d < 8; d++) {
            float2 qa = __half22float2(q2[d]), ka = __half22float2(k2[d]);
            s += qa.x * ka.x + qa.y * ka.y;
          }
          s += __shfl_xor_sync(0xffffffffu, s, 1);
          s *= 0.17677669529663687f;
          float mx = fmaxf(s, __shfl_xor_sync(0xffffffffu, s, 2));
          mx = fmaxf(mx, __shfl_xor_sync(0xffffffffu, mx, 4));
          float pr = expf(s - mx);
          float dn = pr + __shfl_xor_sync(0xffffffffu, pr, 2);
          dn += __shfl_xor_sync(0xffffffffu, dn, 4);
          pr /= dn;
          float pv[16];
#pragma unroll
          for (int d = 0; d < 8; d++) {
            float2 va = __half22float2(v2[d]);
            float x0 = pr * va.x, x1 = pr * va.y;
            x0 += __shfl_xor_sync(0xffffffffu, x0, 2);
            x1 += __shfl_xor_sync(0xffffffffu, x1, 2);
            x0 += __shfl_xor_sync(0xffffffffu, x0, 4);
            x1 += __shfl_xor_sync(0xffffffffu, x1, 4);
            pv[2 * d] = x0; pv[2 * d + 1] = x1;
          }
          if (kt == 0) {
            __half2* o2 = (__half2*)(oB + (bi * 4 + qt) * HS + (2 * p + hh) * 32 + dh * 16);
#pragma unroll
            for (int d = 0; d < 8; d++)
              o2[d] = __floats2half2_rn(pv[2 * d], pv[2 * d + 1]);
          }
        }
      }
      __syncthreads();
    }

    // ========== square GEMMs: warp owns 32 cols, barrier-free mainloop =====
#pragma unroll 1
    for (int gg = 0; gg < 3; gg++) {
      const __half* gw = (gg == 0)   ? g_Wo + (size_t)l * kD * kD
                         : (gg == 1) ? g_W1 + (size_t)l * kD * kD
                                     : g_W2 + (size_t)l * kD * kD;
      const uint32_t aBase = (gg == 1) ? hA_u : oB_u;
      const int col0 = warp * 32;
      load_w_warp(wbBase, gw, 0, col0, lane);
      cp_commit();
      load_w_warp(wbBase + WB_CHUNK, gw, 1, col0, lane);
      cp_commit();
      float acc[2][4][4];
#pragma unroll
      for (int t = 0; t < 2; t++)
#pragma unroll
        for (int i = 0; i < 4; i++)
#pragma unroll
          for (int j = 0; j < 4; j++) acc[t][i][j] = 0.f;
#pragma unroll 4
      for (int c = 0; c < NCH; c++) {
        if (c + 2 < NCH)
          load_w_warp(wbBase + ((c + 2) % 3) * WB_CHUNK, gw, c + 2, col0, lane);
        cp_commit();
        cp_wait<2>();
        __syncwarp();
        const uint32_t bA = wbBase + (c % 3) * WB_CHUNK;
        uint32_t a[2][4];
#pragma unroll
        for (int t = 0; t < 2; t++)
          ldsm4(a[t][0], a[t][1], a[t][2], a[t][3],
                aBase + aA[t] + (uint32_t)((c * CHK) << 1));
        uint32_t b0, b1, b2, b3, c0, c1, c2, c3;
        ldsm4t(b0, b1, b2, b3, bA + bOff);
        ldsm4t(c0, c1, c2, c3, bA + bOff2 + (uint32_t)(((lane >> 4) << 3) << 1));
#pragma unroll
        for (int t = 0; t < 2; t++) {
          mma16816(acc[t][0], a[t][0], a[t][1], a[t][2], a[t][3], b0, b1);
          mma16816(acc[t][1], a[t][0], a[t][1], a[t][2], a[t][3], b2, b3);
          mma16816(acc[t][2], a[t][0], a[t][1], a[t][2], a[t][3], c0, c1);
          mma16816(acc[t][3], a[t][0], a[t][1], a[t][2], a[t][3], c2, c3);
        }
      }
      // epilogues
      if (gg == 1) {  // GELU -> oB
        const float* bb = b1 + l * 256;
#pragma unroll
        for (int t = 0; t < 2; t++)
#pragma unroll
          for (int n = 0; n < 4; n++) {
            int col = warp * 32 + n * 8 + cl;
            float bv0 = bb[col], bv1 = bb[col + 1];
#pragma unroll
            for (int q = 0; q < 2; q++) {
              int row = t * 16 + q * 8 + rb;
              float v0 = acc[t][n][2 * q] + bv0, v1 = acc[t][n][2 * q + 1] + bv1;
              *(__half2*)(oB + row * HS + col) = __floats2half2_rn(
                  0.5f * v0 * (1.0f + erff(v0 * 0.7071067811865475f)),
                  0.5f * v1 * (1.0f + erff(v1 * 0.7071067811865475f)));
            }
          }
      } else {  // residual add
        const float* bb = (gg == 0) ? bo + l * 256 : b2 + l * 256;
#pragma unroll
        for (int t = 0; t < 2; t++)
#pragma unroll
          for (int n = 0; n < 4; n++) {
            int col = warp * 32 + n * 8 + cl;
            float bv0 = bb[col], bv1 = bb[col + 1];
#pragma unroll
            for (int q = 0; q < 2; q++) {
              int row = t * 16 + q * 8 + rb;
              xs[row * XSD + col] += acc[t][n][2 * q] + bv0;
              xs[row * XSD + col + 1] += acc[t][n][2 * q + 1] + bv1;
            }
          }
      }
      __syncthreads();
      if (gg == 0) {  // LN2 -> hA for W1
        ln_to_half(xs, hA, ln2_g + l * 256, ln2_b + l * 256, tid);
        __syncthreads();
      }
    }
  }

  // ---- final LN, mean over 4 tokens, output LN ----
  ln_inplace(xs, final_g, final_b, tid);
  __syncthreads();
  {
    int b = warp;
    const float* base = xs + b * 4 * XSD;
    float v[8], s = 0.f, s2 = 0.f;
#pragma unroll
    for (int j = 0; j < 8; j++) {
      int c = lane * 8 + j;
      float m = 0.25f * (base[c] + base[XSD + c] + base[2 * XSD + c] + base[3 * XSD + c]);
      v[j] = m; s += m; s2 += m * m;
    }
#pragma unroll
    for (int o = 16; o > 0; o >>= 1) {
      s += __shfl_xor_sync(0xffffffffu, s, o);
      s2 += __shfl_xor_sync(0xffffffffu, s2, o);
    }
    float mean = s * (1.f / 256.f);
    float rstd = rsqrtf(s2 * (1.f / 256.f) - mean * mean + 1e-5f);
#pragma unroll
    for (int j = 0; j < 8; j++) {
      int c = lane * 8 + j;
      out[(size_t)(gb0 + b) * 256 + c] = (v[j] - mean) * rstd * out_g[c] + out_b[c];
    }
  }
}

extern "C" void kernel_launch(void* const* d_in, const int* in_sizes, int n_in,
                              void* d_out, int out_size) {
  (void)in_sizes; (void)n_in; (void)out_size;
  const float* global_emb = (const float*)d_in[0];
  const float* pert_emb   = (const float*)d_in[1];
  const float* sym_feat   = (const float*)d_in[2];
  const float* ppi_feat   = (const float*)d_in[3];
  const float* sym_W      = (const float*)d_in[4];
  const float* sym_b      = (const float*)d_in[5];
  const float* sym_ln_g   = (const float*)d_in[6];
  const float* sym_ln_b   = (const float*)d_in[7];
  const float* tte        = (const float*)d_in[8];
  const float* Wqkv       = (const float*)d_in[9];
  const float* bqkv       = (const float*)d_in[10];
  const float* Wo         = (const float*)d_in[11];
  const float* bo         = (const float*)d_in[12];
  const float* ln1_g      = (const float*)d_in[13];
  const float* ln1_b      = (const float*)d_in[14];
  const float* ln2_g      = (const float*)d_in[15];
  const float* ln2_b      = (const float*)d_in[16];
  const float* W1         = (const float*)d_in[17];
  const float* b1         = (const float*)d_in[18];
  const float* W2         = (const float*)d_in[19];
  const float* b2         = (const float*)d_in[20];
  const float* final_g    = (const float*)d_in[21];
  const float* final_b    = (const float*)d_in[22];
  const float* out_g      = (const float*)d_in[23];
  const float* out_b      = (const float*)d_in[24];

  static bool attr_done = false;
  if (!attr_done) {
    cudaFuncSetAttribute(fused_kernel, cudaFuncAttributeMaxDynamicSharedMemorySize,
                         SMEM_BYTES);
    attr_done = true;
  }

  const int NTOT = kL * kD * 3 * kD + 3 * kL * kD * kD;
  prep_weights_kernel<<<(NTOT + 255) / 256, 256>>>(Wqkv, Wo, W1, W2);
  fused_kernel<<<kB / kMB, kNT, SMEM_BYTES>>>(
      global_emb, pert_emb, sym_feat, ppi_feat, sym_W, sym_b, sym_ln_g, sym_ln_b,
      tte, bqkv, bo, ln1_g, ln1_b, ln2_g, ln2_b, b1, b2, final_g, final_b, out_g,
      out_b, (float*)d_out);
}

// round 16
// speedup vs baseline: 1.9770x; 1.3863x over previous
#include <cuda_runtime.h>
#include <cuda_fp16.h>
#include <stdint.h>
#include <math.h>

#define kD 256
#define kH 8
#define kL 3
#define kB 32768
#define kMB 8
#define kNT 256
#define HS 264    // A-operand half stride
#define XSD 260   // xs float stride
#define QS 392    // qkv fp16 stride (4 heads * 96 + pad)

#define XO 0
#define HAO 33280
#define QOF 50176
#define OOF 75264
#define SMEM_BYTES 92160

// Weights pre-swizzled into mma.m16n8k16 B-fragment order:
// [tile][k16][lane][4 halves]  where the 4 halves are exactly lane's {b0,b1}.
__device__ __align__(16) __half g_WqkvF[kL * 96 * 16 * 32 * 4];  // gathered head order
__device__ __align__(16) __half g_WoF[kL * 32 * 16 * 32 * 4];
__device__ __align__(16) __half g_W1F[kL * 32 * 16 * 32 * 4];
__device__ __align__(16) __half g_W2F[kL * 32 * 16 * 32 * 4];

__global__ void prep_weights_kernel(const float* __restrict__ wqkv,
                                    const float* __restrict__ wo,
                                    const float* __restrict__ w1,
                                    const float* __restrict__ w2) {
  int idx = blockIdx.x * blockDim.x + threadIdx.x;
  const int SQ = kL * 96 * 16 * 32;  // 147456 fragment slots (4 halves each)
  const int SO = kL * 32 * 16 * 32;  // 49152 per square weight
  if (idx < SQ) {
    int lane = idx & 31, kk = (idx >> 5) & 15, tl = idx >> 9;
    int t = tl % 96, l = tl / 96;
    int head = t / 12, jm = t % 12, part = jm >> 2, sub = jm & 3;
    int col = part * 256 + head * 32 + sub * 8 + (lane >> 2);
    int kr = kk * 16 + (lane & 3) * 2;
    const float* src = wqkv + (size_t)l * 256 * 768;
    __half* dst = g_WqkvF + (size_t)idx * 4;
    dst[0] = __float2half_rn(src[(size_t)kr * 768 + col]);
    dst[1] = __float2half_rn(src[(size_t)(kr + 1) * 768 + col]);
    dst[2] = __float2half_rn(src[(size_t)(kr + 8) * 768 + col]);
    dst[3] = __float2half_rn(src[(size_t)(kr + 9) * 768 + col]);
    return;
  }
  idx -= SQ;
  if (idx >= 3 * SO) return;
  int which = idx / SO;
  int r = idx - which * SO;
  const float* srcA = (which == 0) ? wo : (which == 1) ? w1 : w2;
  __half* dstA = (which == 0) ? g_WoF : (which == 1) ? g_W1F : g_W2F;
  int lane = r & 31, kk = (r >> 5) & 15, tl = r >> 9;
  int t = tl & 31, l = tl >> 5;
  int col = t * 8 + (lane >> 2);
  int kr = kk * 16 + (lane & 3) * 2;
  const float* src = srcA + (size_t)l * 256 * 256;
  __half* dst = dstA + (size_t)r * 4;
  dst[0] = __float2half_rn(src[(size_t)kr * 256 + col]);
  dst[1] = __float2half_rn(src[(size_t)(kr + 1) * 256 + col]);
  dst[2] = __float2half_rn(src[(size_t)(kr + 8) * 256 + col]);
  dst[3] = __float2half_rn(src[(size_t)(kr + 9) * 256 + col]);
}

__device__ __forceinline__ uint32_t smem_u32(const void* p) {
  uint32_t a;
  asm volatile("{ .reg .u64 t; cvta.to.shared.u64 t, %1; cvt.u32.u64 %0, t; }"
               : "=r"(a) : "l"(p));
  return a;
}
__device__ __forceinline__ void ldsm4(uint32_t& r0, uint32_t& r1, uint32_t& r2,
                                      uint32_t& r3, uint32_t a) {
  asm volatile("ldmatrix.sync.aligned.m8n8.x4.shared.b16 {%0,%1,%2,%3}, [%4];"
               : "=r"(r0), "=r"(r1), "=r"(r2), "=r"(r3) : "r"(a));
}
__device__ __forceinline__ void mma16816(float* c, uint32_t a0, uint32_t a1,
                                         uint32_t a2, uint32_t a3, uint32_t b0,
                                         uint32_t b1) {
  asm volatile(
      "mma.sync.aligned.m16n8k16.row.col.f32.f16.f16.f32 "
      "{%0,%1,%2,%3}, {%4,%5,%6,%7}, {%8,%9}, {%0,%1,%2,%3};"
      : "+f"(c[0]), "+f"(c[1]), "+f"(c[2]), "+f"(c[3])
      : "r"(a0), "r"(a1), "r"(a2), "r"(a3), "r"(b0), "r"(b1));
}

// C[32, NT*8] += A[32,256](smem) @ W(fragment gmem). B streamed gmem->regs.
template <int NT>
__device__ __forceinline__ void gemm_frag(uint32_t aBase, const uint32_t* aA,
                                          const __half* __restrict__ wf,
                                          float (*acc)[4]) {
  uint2 breg[2][NT];
#pragma unroll
  for (int n = 0; n < NT; n++) breg[0][n] = *(const uint2*)(wf + n * 2048);
#pragma unroll
  for (int n = 0; n < NT; n++) breg[1][n] = *(const uint2*)(wf + n * 2048 + 128);
#pragma unroll
  for (int k = 0; k < 16; k++) {
    uint32_t a[2][4];
#pragma unroll
    for (int t = 0; t < 2; t++)
      ldsm4(a[t][0], a[t][1], a[t][2], a[t][3], aBase + aA[t] + (uint32_t)(k * 32));
#pragma unroll
    for (int n = 0; n < NT; n++) {
      uint2 b = breg[k & 1][n];
#pragma unroll
      for (int t = 0; t < 2; t++)
        mma16816(acc[t * NT + n], a[t][0], a[t][1], a[t][2], a[t][3], b.x, b.y);
    }
    if (k + 2 < 16) {
#pragma unroll
      for (int n = 0; n < NT; n++)
        breg[k & 1][n] = *(const uint2*)(wf + n * 2048 + (k + 2) * 128);
    }
  }
}

__device__ __forceinline__ void row_stats(const float* __restrict__ row, int lane,
                                          float v[8], float& mean, float& rstd) {
  const float4* r4 = (const float4*)row;
  float4 a = r4[lane * 2], b = r4[lane * 2 + 1];
  v[0] = a.x; v[1] = a.y; v[2] = a.z; v[3] = a.w;
  v[4] = b.x; v[5] = b.y; v[6] = b.z; v[7] = b.w;
  float s = 0.f, s2 = 0.f;
#pragma unroll
  for (int j = 0; j < 8; j++) { s += v[j]; s2 += v[j] * v[j]; }
#pragma unroll
  for (int o = 16; o > 0; o >>= 1) {
    s += __shfl_xor_sync(0xffffffffu, s, o);
    s2 += __shfl_xor_sync(0xffffffffu, s2, o);
  }
  mean = s * (1.f / 256.f);
  rstd = rsqrtf(s2 * (1.f / 256.f) - mean * mean + 1e-5f);
}

__device__ __forceinline__ void ln_to_half(const float* __restrict__ xs,
                                           __half* __restrict__ dst,
                                           const float* __restrict__ g,
                                           const float* __restrict__ bt, int tid) {
  int warp = tid >> 5, lane = tid & 31;
#pragma unroll
  for (int i = 0; i < 4; i++) {
    int r = warp * 4 + i;
    float v[8], mean, rstd;
    row_stats(xs + r * XSD, lane, v, mean, rstd);
    __half2* d2 = (__half2*)(dst + r * HS + lane * 8);
#pragma unroll
    for (int j = 0; j < 4; j++) {
      int c = lane * 8 + 2 * j;
      d2[j] = __floats2half2_rn((v[2 * j] - mean) * rstd * g[c] + bt[c],
                                (v[2 * j + 1] - mean) * rstd * g[c + 1] + bt[c + 1]);
    }
  }
}

__device__ __forceinline__ void ln_inplace(float* __restrict__ xs,
                                           const float* __restrict__ g,
                                           const float* __restrict__ bt, int tid) {
  int warp = tid >> 5, lane = tid & 31;
#pragma unroll
  for (int i = 0; i < 4; i++) {
    int r = warp * 4 + i;
    float v[8], mean, rstd;
    row_stats(xs + r * XSD, lane, v, mean, rstd);
#pragma unroll
    for (int j = 0; j < 8; j++) {
      int c = lane * 8 + j;
      xs[r * XSD + c] = (v[j] - mean) * rstd * g[c] + bt[c];
    }
  }
}

__global__ void __launch_bounds__(kNT, 2) fused_kernel(
    const float* __restrict__ global_emb, const float* __restrict__ pert_emb,
    const float* __restrict__ sym_feat, const float* __restrict__ ppi_feat,
    const float* __restrict__ sym_W, const float* __restrict__ sym_b,
    const float* __restrict__ sym_ln_g, const float* __restrict__ sym_ln_b,
    const float* __restrict__ tte, const float* __restrict__ bqkv,
    const float* __restrict__ bo, const float* __restrict__ ln1_g,
    const float* __restrict__ ln1_b, const float* __restrict__ ln2_g,
    const float* __restrict__ ln2_b, const float* __restrict__ b1,
    const float* __restrict__ b2, const float* __restrict__ final_g,
    const float* __restrict__ final_b, const float* __restrict__ out_g,
    const float* __restrict__ out_b, float* __restrict__ out) {
  extern __shared__ char smem[];
  float* xs = (float*)(smem + XO);
  __half* hA = (__half*)(smem + HAO);
  __half* qk16 = (__half*)(smem + QOF);
  __half* oB = (__half*)(smem + OOF);

  const int tid = threadIdx.x, warp = tid >> 5, lane = tid & 31;
  const int gb0 = blockIdx.x * kMB;
  const uint32_t hA_u = smem_u32(hA), oB_u = smem_u32(oB);

  // ---- initial x: tokens 0,1,3 + tte; stage sym_feat ----
#pragma unroll
  for (int i = 0; i < 8; i++) {
    int u = tid + kNT * i;
    int b = u >> 8, c = u & 255;
    xs[(b * 4 + 0) * XSD + c] = global_emb[(size_t)(gb0 + b) * 256 + c] + tte[c];
    xs[(b * 4 + 1) * XSD + c] = pert_emb[(size_t)(gb0 + b) * 256 + c] + tte[256 + c];
    xs[(b * 4 + 3) * XSD + c] = ppi_feat[(size_t)(gb0 + b) * 256 + c] + tte[768 + c];
  }
  {
    float* stage = (float*)qk16;
#pragma unroll
    for (int i = 0; i < 2; i++) {
      int u = tid + kNT * i;
      stage[u] = sym_feat[(size_t)gb0 * 64 + u];
    }
  }
  __syncthreads();
  {  // sym projection fp32
    const float* stage = (const float*)qk16;
#pragma unroll
    for (int i = 0; i < 8; i++) {
      int u = tid + kNT * i;
      int b = u >> 8, c = u & 255;
      const float* sf = stage + b * 64;
      float acc = sym_b[c];
#pragma unroll 8
      for (int k = 0; k < 64; k++) acc += sf[k] * sym_W[k * 256 + c];
      xs[(b * 4 + 2) * XSD + c] = acc;
    }
  }
  __syncthreads();
  {  // sym LN + tte
    int r = warp * 4 + 2;
    float v[8], mean, rstd;
    row_stats(xs + r * XSD, lane, v, mean, rstd);
#pragma unroll
    for (int j = 0; j < 8; j++) {
      int c = lane * 8 + j;
      xs[r * XSD + c] = (v[j] - mean) * rstd * sym_ln_g[c] + sym_ln_b[c] + tte[512 + c];
    }
  }
  __syncthreads();

  const int rb = lane >> 2;
  const int cl = 2 * (lane & 3);
  uint32_t aA[2];
#pragma unroll
  for (int t = 0; t < 2; t++)
    aA[t] = (uint32_t)(((t * 16 + (lane & 15)) * HS + ((lane >> 4) << 3)) << 1);

  for (int l = 0; l < kL; l++) {
    ln_to_half(xs, hA, ln1_g + l * 256, ln1_b + l * 256, tid);
    __syncthreads();

    // ========== QKV: 2 phases x 4 heads, B fragments streamed from gmem ====
    for (int p = 0; p < 2; p++) {
      const __half* qf =
          g_WqkvF + (size_t)l * 196608 + (size_t)(p * 48 + warp * 6) * 2048 + lane * 4;
      float acc[12][4];
#pragma unroll
      for (int i = 0; i < 12; i++)
#pragma unroll
        for (int j = 0; j < 4; j++) acc[i][j] = 0.f;
      gemm_frag<6>(hA_u, aA, qf, acc);

      // epilogue -> qk16 fp16 (+bias), gathered layout: [head&3][q|k|v]
      const float* bq = bqkv + l * 768;
#pragma unroll
      for (int t = 0; t < 2; t++)
#pragma unroll
        for (int n = 0; n < 6; n++) {
          int T = p * 48 + warp * 6 + n;
          int head = T / 12, jm = T % 12, part = jm >> 2, sub = jm & 3;
          int lcol = (head & 3) * 96 + part * 32 + sub * 8 + cl;
          int bc = part * 256 + head * 32 + sub * 8 + cl;
          float bv0 = bq[bc], bv1 = bq[bc + 1];
          int row = t * 16 + rb;
          *(__half2*)(qk16 + row * QS + lcol) =
              __floats2half2_rn(acc[t * 6 + n][0] + bv0, acc[t * 6 + n][1] + bv1);
          *(__half2*)(qk16 + (row + 8) * QS + lcol) =
              __floats2half2_rn(acc[t * 6 + n][2] + bv0, acc[t * 6 + n][3] + bv1);
        }
      __syncthreads();

      // attention for 4 heads: one warp per sequence
      {
        const int bi = warp;
        const int qt = lane >> 3, kt = (lane >> 1) & 3, dh = lane & 1;
#pragma unroll
        for (int hh = 0; hh < 4; hh++) {
          const __half2* q2 = (const __half2*)(qk16 + (bi * 4 + qt) * QS + hh * 96 + dh * 16);
          const __half2* k2 = (const __half2*)(qk16 + (bi * 4 + kt) * QS + hh * 96 + 32 + dh * 16);
          const __half2* v2 = (const __half2*)(qk16 + (bi * 4 + kt) * QS + hh * 96 + 64 + dh * 16);
          float s = 0.f;
#pragma unroll
          for (int d = 0; d < 8; d++) {
            float2 qa = __half22float2(q2[d]), ka = __half22float2(k2[d]);
            s += qa.x * ka.x + qa.y * ka.y;
          }
          s += __shfl_xor_sync(0xffffffffu, s, 1);
          s *= 0.17677669529663687f;
          float mx = fmaxf(s, __shfl_xor_sync(0xffffffffu, s, 2));
          mx = fmaxf(mx, __shfl_xor_sync(0xffffffffu, mx, 4));
          float pr = expf(s - mx);
          float dn = pr + __shfl_xor_sync(0xffffffffu, pr, 2);
          dn += __shfl_xor_sync(0xffffffffu, dn, 4);
          pr /= dn;
          float pv[16];
#pragma unroll
          for (int d = 0; d < 8; d++) {
            float2 va = __half22float2(v2[d]);
            float x0 = pr * va.x, x1 = pr * va.y;
            x0 += __shfl_xor_sync(0xffffffffu, x0, 2);
            x1 += __shfl_xor_sync(0xffffffffu, x1, 2);
            x0 += __shfl_xor_sync(0xffffffffu, x0, 4);
            x1 += __shfl_xor_sync(0xffffffffu, x1, 4);
            pv[2 * d] = x0; pv[2 * d + 1] = x1;
          }
          if (kt == 0) {
            __half2* o2 = (__half2*)(oB + (bi * 4 + qt) * HS + (p * 4 + hh) * 32 + dh * 16);
#pragma unroll
            for (int d = 0; d < 8; d++)
              o2[d] = __floats2half2_rn(pv[2 * d], pv[2 * d + 1]);
          }
        }
      }
      __syncthreads();
    }

    // ========== square GEMMs: warp owns 32 cols, B fragments from gmem =====
#pragma unroll 1
    for (int gg = 0; gg < 3; gg++) {
      const __half* wf =
          ((gg == 0) ? g_WoF : (gg == 1) ? g_W1F : g_W2F) + (size_t)l * 65536 +
          (size_t)(warp * 4) * 2048 + lane * 4;
      const uint32_t aBase = (gg == 1) ? hA_u : oB_u;
      float acc[8][4];
#pragma unroll
      for (int i = 0; i < 8; i++)
#pragma unroll
        for (int j = 0; j < 4; j++) acc[i][j] = 0.f;
      gemm_frag<4>(aBase, aA, wf, acc);

      if (gg == 1) {  // GELU -> oB
        const float* bb = b1 + l * 256;
#pragma unroll
        for (int t = 0; t < 2; t++)
#pragma unroll
          for (int n = 0; n < 4; n++) {
            int col = warp * 32 + n * 8 + cl;
            float bv0 = bb[col], bv1 = bb[col + 1];
#pragma unroll
            for (int q = 0; q < 2; q++) {
              int row = t * 16 + q * 8 + rb;
              float v0 = acc[t * 4 + n][2 * q] + bv0, v1 = acc[t * 4 + n][2 * q + 1] + bv1;
              *(__half2*)(oB + row * HS + col) = __floats2half2_rn(
                  0.5f * v0 * (1.0f + erff(v0 * 0.7071067811865475f)),
                  0.5f * v1 * (1.0f + erff(v1 * 0.7071067811865475f)));
            }
          }
      } else {  // residual add
        const float* bb = (gg == 0) ? bo + l * 256 : b2 + l * 256;
#pragma unroll
        for (int t = 0; t < 2; t++)
#pragma unroll
          for (int n = 0; n < 4; n++) {
            int col = warp * 32 + n * 8 + cl;
            float bv0 = bb[col], bv1 = bb[col + 1];
#pragma unroll
            for (int q = 0; q < 2; q++) {
              int row = t * 16 + q * 8 + rb;
              xs[row * XSD + col] += acc[t * 4 + n][2 * q] + bv0;
              xs[row * XSD + col + 1] += acc[t * 4 + n][2 * q + 1] + bv1;
            }
          }
      }
      __syncthreads();
      if (gg == 0) {  // LN2 -> hA for W1
        ln_to_half(xs, hA, ln2_g + l * 256, ln2_b + l * 256, tid);
        __syncthreads();
      }
    }
  }

  // ---- final LN, mean over 4 tokens, output LN ----
  ln_inplace(xs, final_g, final_b, tid);
  __syncthreads();
  {
    int b = warp;
    const float* base = xs + b * 4 * XSD;
    float v[8], s = 0.f, s2 = 0.f;
#pragma unroll
    for (int j = 0; j < 8; j++) {
      int c = lane * 8 + j;
      float m = 0.25f * (base[c] + base[XSD + c] + base[2 * XSD + c] + base[3 * XSD + c]);
      v[j] = m; s += m; s2 += m * m;
    }
#pragma unroll
    for (int o = 16; o > 0; o >>= 1) {
      s += __shfl_xor_sync(0xffffffffu, s, o);
      s2 += __shfl_xor_sync(0xffffffffu, s2, o);
    }
    float mean = s * (1.f / 256.f);
    float rstd = rsqrtf(s2 * (1.f / 256.f) - mean * mean + 1e-5f);
#pragma unroll
    for (int j = 0; j < 8; j++) {
      int c = lane * 8 + j;
      out[(size_t)(gb0 + b) * 256 + c] = (v[j] - mean) * rstd * out_g[c] + out_b[c];
    }
  }
}

extern "C" void kernel_launch(void* const* d_in, const int* in_sizes, int n_in,
                              void* d_out, int out_size) {
  (void)in_sizes; (void)n_in; (void)out_size;
  const float* global_emb = (const float*)d_in[0];
  const float* pert_emb   = (const float*)d_in[1];
  const float* sym_feat   = (const float*)d_in[2];
  const float* ppi_feat   = (const float*)d_in[3];
  const float* sym_W      = (const float*)d_in[4];
  const float* sym_b      = (const float*)d_in[5];
  const float* sym_ln_g   = (const float*)d_in[6];
  const float* sym_ln_b   = (const float*)d_in[7];
  const float* tte        = (const float*)d_in[8];
  const float* Wqkv       = (const float*)d_in[9];
  const float* bqkv       = (const float*)d_in[10];
  const float* Wo         = (const float*)d_in[11];
  const float* bo         = (const float*)d_in[12];
  const float* ln1_g      = (const float*)d_in[13];
  const float* ln1_b      = (const float*)d_in[14];
  const float* ln2_g      = (const float*)d_in[15];
  const float* ln2_b      = (const float*)d_in[16];
  const float* W1         = (const float*)d_in[17];
  const float* b1         = (const float*)d_in[18];
  const float* W2         = (const float*)d_in[19];
  const float* b2         = (const float*)d_in[20];
  const float* final_g    = (const float*)d_in[21];
  const float* final_b    = (const float*)d_in[22];
  const float* out_g      = (const float*)d_in[23];
  const float* out_b      = (const float*)d_in[24];

  static bool attr_done = false;
  if (!attr_done) {
    cudaFuncSetAttribute(fused_kernel, cudaFuncAttributeMaxDynamicSharedMemorySize,
                         SMEM_BYTES);
    attr_done = true;
  }

  const int NSLOTS = kL * 96 * 16 * 32 + 3 * kL * 32 * 16 * 32;  // 294912
  prep_weights_kernel<<<(NSLOTS + 255) / 256, 256>>>(Wqkv, Wo, W1, W2);
  fused_kernel<<<kB / kMB, kNT, SMEM_BYTES>>>(
      global_emb, pert_emb, sym_feat, ppi_feat, sym_W, sym_b, sym_ln_g, sym_ln_b,
      tte, bqkv, bo, ln1_g, ln1_b, ln2_g, ln2_b, b1, b2, final_g, final_b, out_g,
      out_b, (float*)d_out);
}